// round 1
// baseline (speedup 1.0000x reference)
#include <cuda_runtime.h>
#include <math.h>

// Problem constants
#define Bv   4
#define Tv   4096
#define Dv   1024
#define Hv   16
#define HDv  64
#define Cv   128
#define NCv  32            // Tv / Cv
#define Mv   (Bv*Tv)       // 16384

// ---------------------------------------------------------------------------
// Scratch (device globals; no allocation allowed)
// ---------------------------------------------------------------------------
__device__ float g_Q[(size_t)Mv * Dv];   // feature-mapped Q, layout (B*T, H*HD)
__device__ float g_K[(size_t)Mv * Dv];   // feature-mapped K
__device__ float g_V[(size_t)Mv * Dv];   // V
__device__ float g_Y[(size_t)Mv * Dv];   // attention output (B*T, H*HD)
__device__ float g_S[(size_t)Bv * Hv * NCv * HDv * HDv];  // per-chunk states -> exclusive prefix
__device__ float g_z[(size_t)Bv * Hv * NCv * HDv];        // per-chunk z -> exclusive prefix

// ---------------------------------------------------------------------------
// SGEMM: C[M,N] = A[M,K] @ B[K,N], M=16384, N=K=1024.
// 128x128 block tile, BK=8, 256 threads, 8x8 per-thread tile (split 4+4),
// double-buffered shared memory, optional (elu+1) epilogue.
// asel: 0 -> A = Aext (x), 1 -> A = g_Y
// csel: 0 -> g_Q, 1 -> g_K, 2 -> g_V, 3 -> Cext (d_out)
// ---------------------------------------------------------------------------
__global__ __launch_bounds__(256, 2)
void sgemm_kernel(const float* __restrict__ Aext, const float* __restrict__ Bw,
                  float* __restrict__ Cext, int asel, int csel, int fmap)
{
    const float* A = asel ? g_Y : Aext;
    float* C = (csel == 0) ? g_Q : (csel == 1) ? g_K : (csel == 2) ? g_V : Cext;
    const int K = 1024, N = 1024;

    __shared__ float As[2][8][128];  // transposed: As[k][m]
    __shared__ float Bs[2][8][128];  // Bs[k][n]

    int t  = threadIdx.x;
    int m0 = blockIdx.x * 128;
    int n0 = blockIdx.y * 128;

    int arow = t >> 1,  acol = (t & 1) << 2;   // A tile load: 128 rows x 8 cols
    int brow = t >> 5,  bcol = (t & 31) << 2;  // B tile load: 8 rows x 128 cols

    const float* Ag = A  + (size_t)(m0 + arow) * K + acol;
    const float* Bg = Bw + (size_t)brow * N + n0 + bcol;

    float4 av = *(const float4*)Ag;
    float4 bv = *(const float4*)Bg;
    As[0][acol + 0][arow] = av.x;
    As[0][acol + 1][arow] = av.y;
    As[0][acol + 2][arow] = av.z;
    As[0][acol + 3][arow] = av.w;
    *(float4*)&Bs[0][brow][bcol] = bv;
    __syncthreads();

    int tx = t & 15, ty = t >> 4;

    float acc[8][8];
#pragma unroll
    for (int i = 0; i < 8; i++)
#pragma unroll
        for (int j = 0; j < 8; j++) acc[i][j] = 0.f;

    const int NK = K / 8;
    for (int kt = 0; kt < NK; kt++) {
        int cur = kt & 1;
        if (kt + 1 < NK) {
            av = *(const float4*)(Ag + (size_t)(kt + 1) * 8);
            bv = *(const float4*)(Bg + (size_t)(kt + 1) * 8 * N);
        }
#pragma unroll
        for (int kk = 0; kk < 8; kk++) {
            float4 a0 = *(const float4*)&As[cur][kk][ty * 4];
            float4 a1 = *(const float4*)&As[cur][kk][64 + ty * 4];
            float4 b0 = *(const float4*)&Bs[cur][kk][tx * 4];
            float4 b1 = *(const float4*)&Bs[cur][kk][64 + tx * 4];
            float ar[8] = {a0.x, a0.y, a0.z, a0.w, a1.x, a1.y, a1.z, a1.w};
            float br[8] = {b0.x, b0.y, b0.z, b0.w, b1.x, b1.y, b1.z, b1.w};
#pragma unroll
            for (int i = 0; i < 8; i++)
#pragma unroll
                for (int j = 0; j < 8; j++)
                    acc[i][j] += ar[i] * br[j];
        }
        if (kt + 1 < NK) {
            int nxt = cur ^ 1;
            As[nxt][acol + 0][arow] = av.x;
            As[nxt][acol + 1][arow] = av.y;
            As[nxt][acol + 2][arow] = av.z;
            As[nxt][acol + 3][arow] = av.w;
            *(float4*)&Bs[nxt][brow][bcol] = bv;
        }
        __syncthreads();
    }

#pragma unroll
    for (int i = 0; i < 8; i++) {
        int mi = (i < 4) ? (ty * 4 + i) : (64 + ty * 4 + (i - 4));
        float* Crow = C + (size_t)(m0 + mi) * N + n0;
#pragma unroll
        for (int hb = 0; hb < 2; hb++) {
            float v0 = acc[i][hb * 4 + 0];
            float v1 = acc[i][hb * 4 + 1];
            float v2 = acc[i][hb * 4 + 2];
            float v3 = acc[i][hb * 4 + 3];
            if (fmap) {  // elu(x)+1 : x>0 -> x+1 ; else exp(x)
                v0 = v0 > 0.f ? v0 + 1.f : expf(v0);
                v1 = v1 > 0.f ? v1 + 1.f : expf(v1);
                v2 = v2 > 0.f ? v2 + 1.f : expf(v2);
                v3 = v3 > 0.f ? v3 + 1.f : expf(v3);
            }
            float4 o; o.x = v0; o.y = v1; o.z = v2; o.w = v3;
            *(float4*)(Crow + hb * 64 + tx * 4) = o;
        }
    }
}

// ---------------------------------------------------------------------------
// Phase A: per (b,h,chunk) local state  S_c = K_c^T V_c  (64x64), z_c = sum_t k_t
// grid = B*H*NC blocks, 256 threads. Static smem (two 64-row halves).
// ---------------------------------------------------------------------------
__global__ __launch_bounds__(256)
void phaseA_kernel()
{
    __shared__ float Ks[64][65];
    __shared__ float Vs[64][65];

    int blk = blockIdx.x;
    int c   = blk & (NCv - 1);
    int bh  = blk >> 5;
    int h   = bh & (Hv - 1);
    int b   = bh >> 4;
    int t   = threadIdx.x;
    int tx  = t & 15, ty = t >> 4;

    float acc[4][4];
#pragma unroll
    for (int i = 0; i < 4; i++)
#pragma unroll
        for (int j = 0; j < 4; j++) acc[i][j] = 0.f;
    float zacc = 0.f;

    size_t base = ((size_t)(b * Tv + c * Cv)) * Dv + h * HDv;

    for (int half = 0; half < 2; half++) {
        const float* Kg = g_K + base + (size_t)half * 64 * Dv;
        const float* Vg = g_V + base + (size_t)half * 64 * Dv;
        if (half) __syncthreads();
        for (int i = t; i < 64 * 16; i += 256) {
            int row = i >> 4, col4 = (i & 15) << 2;
            float4 kq = *(const float4*)(Kg + (size_t)row * Dv + col4);
            Ks[row][col4 + 0] = kq.x; Ks[row][col4 + 1] = kq.y;
            Ks[row][col4 + 2] = kq.z; Ks[row][col4 + 3] = kq.w;
            float4 vq = *(const float4*)(Vg + (size_t)row * Dv + col4);
            Vs[row][col4 + 0] = vq.x; Vs[row][col4 + 1] = vq.y;
            Vs[row][col4 + 2] = vq.z; Vs[row][col4 + 3] = vq.w;
        }
        __syncthreads();
        for (int tt = 0; tt < 64; tt++) {
            float kd[4], ve[4];
#pragma unroll
            for (int i = 0; i < 4; i++) kd[i] = Ks[tt][ty * 4 + i];
#pragma unroll
            for (int j = 0; j < 4; j++) ve[j] = Vs[tt][tx * 4 + j];
#pragma unroll
            for (int i = 0; i < 4; i++)
#pragma unroll
                for (int j = 0; j < 4; j++)
                    acc[i][j] += kd[i] * ve[j];
        }
        if (t < 64) {
            for (int tt = 0; tt < 64; tt++) zacc += Ks[tt][t];
        }
    }

    float* Sg = g_S + ((size_t)(bh * NCv + c)) * (HDv * HDv);
#pragma unroll
    for (int i = 0; i < 4; i++)
#pragma unroll
        for (int j = 0; j < 4; j++)
            Sg[(ty * 4 + i) * HDv + tx * 4 + j] = acc[i][j];
    if (t < 64) g_z[(size_t)(bh * NCv + c) * HDv + t] = zacc;
}

// ---------------------------------------------------------------------------
// Phase B: exclusive prefix over the 32 chunks (per (b,h)). 64 blocks.
// ---------------------------------------------------------------------------
__global__ __launch_bounds__(256)
void phaseB_kernel()
{
    int bh = blockIdx.x;
    int t  = threadIdx.x;

    float run[16];
#pragma unroll
    for (int r = 0; r < 16; r++) run[r] = 0.f;

    float* Sg = g_S + (size_t)bh * NCv * (HDv * HDv);
    for (int c = 0; c < NCv; c++) {
        float* p = Sg + (size_t)c * (HDv * HDv);
#pragma unroll
        for (int r = 0; r < 16; r++) {
            int idx = t + (r << 8);
            float v = p[idx];
            p[idx] = run[r];
            run[r] += v;
        }
    }
    if (t < 64) {
        float rz = 0.f;
        float* zg = g_z + (size_t)bh * NCv * HDv;
        for (int c = 0; c < NCv; c++) {
            float v = zg[c * HDv + t];
            zg[c * HDv + t] = rz;
            rz += v;
        }
    }
}

// ---------------------------------------------------------------------------
// Phase C: per (b,h,chunk):
//   A   = tril(Q_c K_c^T)                (128x128)
//   den = rowsum(A) + Q_c z_prev + eps   (128)
//   num = A V_c + Q_c S_prev             (128x64)
//   Y_c = num / den
// Dynamic smem: Q[128][65] K/V[128][65] A[128][132] S[64][65] z[64] den[128]
// ---------------------------------------------------------------------------
#define PHC_SMEM ((128*65 + 128*65 + 128*132 + 64*65 + 64 + 128) * 4)

__global__ __launch_bounds__(256)
void phaseC_kernel()
{
    extern __shared__ float sm[];
    float* Qs  = sm;                 // [128][65]
    float* KVs = Qs + 128 * 65;      // [128][65]  (K first, then reused for V)
    float* Asm = KVs + 128 * 65;     // [128][132]
    float* Ssm = Asm + 128 * 132;    // [64][65]
    float* zsm = Ssm + 64 * 65;      // [64]
    float* dsm = zsm + 64;           // [128]

    int blk = blockIdx.x;
    int c   = blk & (NCv - 1);
    int bh  = blk >> 5;
    int h   = bh & (Hv - 1);
    int b   = bh >> 4;
    int t   = threadIdx.x;

    size_t base = ((size_t)(b * Tv + c * Cv)) * Dv + h * HDv;
    const float* Qg = g_Q + base;
    const float* Kg = g_K + base;

    for (int i = t; i < 128 * 16; i += 256) {
        int row = i >> 4, col4 = (i & 15) << 2;
        float4 q = *(const float4*)(Qg + (size_t)row * Dv + col4);
        Qs[row * 65 + col4 + 0] = q.x; Qs[row * 65 + col4 + 1] = q.y;
        Qs[row * 65 + col4 + 2] = q.z; Qs[row * 65 + col4 + 3] = q.w;
        float4 k = *(const float4*)(Kg + (size_t)row * Dv + col4);
        KVs[row * 65 + col4 + 0] = k.x; KVs[row * 65 + col4 + 1] = k.y;
        KVs[row * 65 + col4 + 2] = k.z; KVs[row * 65 + col4 + 3] = k.w;
    }
    const float* Sg = g_S + ((size_t)(bh * NCv + c)) * (HDv * HDv);
    for (int i = t; i < HDv * HDv; i += 256)
        Ssm[(i >> 6) * 65 + (i & 63)] = Sg[i];
    if (t < 64) zsm[t] = g_z[(size_t)(bh * NCv + c) * HDv + t];
    __syncthreads();

    int tx = t & 15, ty = t >> 4;

    // ---- A = tril(Q K^T) ----
    {
        int i0 = ty * 8, j0 = tx * 8;
        float acc[8][8];
#pragma unroll
        for (int r = 0; r < 8; r++)
#pragma unroll
            for (int s = 0; s < 8; s++) acc[r][s] = 0.f;

        for (int d = 0; d < 64; d++) {
            float qv[8], kv[8];
#pragma unroll
            for (int r = 0; r < 8; r++) qv[r] = Qs[(i0 + r) * 65 + d];
#pragma unroll
            for (int s = 0; s < 8; s++) kv[s] = KVs[(j0 + s) * 65 + d];
#pragma unroll
            for (int r = 0; r < 8; r++)
#pragma unroll
                for (int s = 0; s < 8; s++)
                    acc[r][s] += qv[r] * kv[s];
        }
#pragma unroll
        for (int r = 0; r < 8; r++)
#pragma unroll
            for (int s = 0; s < 8; s++) {
                int gi = i0 + r, gj = j0 + s;
                Asm[gi * 132 + gj] = (gj <= gi) ? acc[r][s] : 0.f;
            }
    }
    __syncthreads();

    // ---- den ----
    if (t < 128) {
        float s1 = 0.f;
        for (int j = 0; j < 128; j++) s1 += Asm[t * 132 + j];
        float s2 = 0.f;
        for (int d = 0; d < 64; d++) s2 += Qs[t * 65 + d] * zsm[d];
        dsm[t] = s1 + s2 + 1e-6f;
    }

    // ---- load V (reuse K buffer) ----
    const float* Vg = g_V + base;
    for (int i = t; i < 128 * 16; i += 256) {
        int row = i >> 4, col4 = (i & 15) << 2;
        float4 v = *(const float4*)(Vg + (size_t)row * Dv + col4);
        KVs[row * 65 + col4 + 0] = v.x; KVs[row * 65 + col4 + 1] = v.y;
        KVs[row * 65 + col4 + 2] = v.z; KVs[row * 65 + col4 + 3] = v.w;
    }
    __syncthreads();

    // ---- num = A@V + Q@S_prev ; Y = num/den ----
    {
        int i0 = ty * 8, e0 = tx * 4;
        float acc[8][4];
#pragma unroll
        for (int r = 0; r < 8; r++)
#pragma unroll
            for (int e = 0; e < 4; e++) acc[r][e] = 0.f;

        for (int j = 0; j < 128; j++) {
            float vv[4];
#pragma unroll
            for (int e = 0; e < 4; e++) vv[e] = KVs[j * 65 + e0 + e];
#pragma unroll
            for (int r = 0; r < 8; r++) {
                float a = Asm[(i0 + r) * 132 + j];
#pragma unroll
                for (int e = 0; e < 4; e++) acc[r][e] += a * vv[e];
            }
        }
        for (int d = 0; d < 64; d++) {
            float sv[4];
#pragma unroll
            for (int e = 0; e < 4; e++) sv[e] = Ssm[d * 65 + e0 + e];
#pragma unroll
            for (int r = 0; r < 8; r++) {
                float q = Qs[(i0 + r) * 65 + d];
#pragma unroll
                for (int e = 0; e < 4; e++) acc[r][e] += q * sv[e];
            }
        }

        float* Yg = g_Y + base;
#pragma unroll
        for (int r = 0; r < 8; r++) {
            float inv = 1.f / dsm[i0 + r];
#pragma unroll
            for (int e = 0; e < 4; e++)
                Yg[(size_t)(i0 + r) * Dv + e0 + e] = acc[r][e] * inv;
        }
    }
}

// ---------------------------------------------------------------------------
// Launch
// ---------------------------------------------------------------------------
extern "C" void kernel_launch(void* const* d_in, const int* in_sizes, int n_in,
                              void* d_out, int out_size)
{
    const float* x  = (const float*)d_in[0];
    const float* Wq = (const float*)d_in[1];
    const float* Wk = (const float*)d_in[2];
    const float* Wv = (const float*)d_in[3];
    const float* Wo = (const float*)d_in[4];
    float* out = (float*)d_out;

    cudaFuncSetAttribute(phaseC_kernel,
                         cudaFuncAttributeMaxDynamicSharedMemorySize, PHC_SMEM);

    dim3 gg(Mv / 128, Dv / 128);
    sgemm_kernel<<<gg, 256>>>(x, Wq, nullptr, 0, 0, 1);  // Q = fmap(x@Wq)
    sgemm_kernel<<<gg, 256>>>(x, Wk, nullptr, 0, 1, 1);  // K = fmap(x@Wk)
    sgemm_kernel<<<gg, 256>>>(x, Wv, nullptr, 0, 2, 0);  // V = x@Wv

    phaseA_kernel<<<Bv * Hv * NCv, 256>>>();
    phaseB_kernel<<<Bv * Hv, 256>>>();
    phaseC_kernel<<<Bv * Hv * NCv, 256, PHC_SMEM>>>();

    sgemm_kernel<<<gg, 256>>>(x, Wo, out, 1, 3, 0);      // out = Y@Wo
}

// round 3
// speedup vs baseline: 1.6921x; 1.6921x over previous
#include <cuda_runtime.h>
#include <cuda_bf16.h>
#include <math.h>
#include <stdint.h>

// Problem constants
#define Bv   4
#define Tv   4096
#define Dv   1024
#define Hv   16
#define HDv  64
#define Cv   128
#define NCv  32            // Tv / Cv
#define Mv   (Bv*Tv)       // 16384

// ---------------------------------------------------------------------------
// Scratch (device globals; no allocation allowed)
// ---------------------------------------------------------------------------
__device__ __align__(16) float g_Q[(size_t)Mv * Dv];
__device__ __align__(16) float g_K[(size_t)Mv * Dv];
__device__ __align__(16) float g_V[(size_t)Mv * Dv];
__device__ __align__(16) float g_Y[(size_t)Mv * Dv];
__device__ __align__(16) float g_S[(size_t)Bv * Hv * NCv * HDv * HDv];
__device__ __align__(16) float g_z[(size_t)Bv * Hv * NCv * HDv];

// bf16 hi/lo split buffers
__device__ __align__(16) __nv_bfloat16 gA_hi[(size_t)Mv * Dv];
__device__ __align__(16) __nv_bfloat16 gA_lo[(size_t)Mv * Dv];
__device__ __align__(16) __nv_bfloat16 gW_hi[4 * 1024 * 1024];  // [wsel][K=1024][N=1024]
__device__ __align__(16) __nv_bfloat16 gW_lo[4 * 1024 * 1024];

// ---------------------------------------------------------------------------
// PTX helpers (sm_80-era: mma.sync / ldmatrix / cp.async — legal on sm_100)
// ---------------------------------------------------------------------------
__device__ __forceinline__ uint32_t smem_u32(const void* p) {
    uint32_t a;
    asm("{ .reg .u64 t; cvta.to.shared.u64 t, %1; cvt.u32.u64 %0, t; }" : "=r"(a) : "l"(p));
    return a;
}

__device__ __forceinline__ void cp_async16(uint32_t saddr, const void* g) {
    asm volatile("cp.async.cg.shared.global [%0], [%1], 16;" :: "r"(saddr), "l"(g) : "memory");
}

__device__ __forceinline__ void ldsm_x4(uint32_t* r, uint32_t addr) {
    asm volatile("ldmatrix.sync.aligned.m8n8.x4.shared.b16 {%0,%1,%2,%3}, [%4];"
                 : "=r"(r[0]), "=r"(r[1]), "=r"(r[2]), "=r"(r[3]) : "r"(addr));
}
__device__ __forceinline__ void ldsm_x4_t(uint32_t* r, uint32_t addr) {
    asm volatile("ldmatrix.sync.aligned.m8n8.x4.trans.shared.b16 {%0,%1,%2,%3}, [%4];"
                 : "=r"(r[0]), "=r"(r[1]), "=r"(r[2]), "=r"(r[3]) : "r"(addr));
}

__device__ __forceinline__ void mma16816(float* c, const uint32_t* a, const uint32_t* b) {
    asm volatile(
        "mma.sync.aligned.m16n8k16.row.col.f32.bf16.bf16.f32 "
        "{%0,%1,%2,%3}, {%4,%5,%6,%7}, {%8,%9}, {%0,%1,%2,%3};"
        : "+f"(c[0]), "+f"(c[1]), "+f"(c[2]), "+f"(c[3])
        : "r"(a[0]), "r"(a[1]), "r"(a[2]), "r"(a[3]), "r"(b[0]), "r"(b[1]));
}

// ---------------------------------------------------------------------------
// fp32 -> bf16 hi/lo conversion (A operand; asel: 0 -> src, 1 -> g_Y)
// ---------------------------------------------------------------------------
__global__ __launch_bounds__(256)
void convA_kernel(const float* __restrict__ src, int asel)
{
    const float* A = asel ? g_Y : src;
    size_t i = ((size_t)blockIdx.x * 256 + threadIdx.x) * 4;
    float4 v = *(const float4*)(A + i);
    float f[4] = {v.x, v.y, v.z, v.w};
    ushort4 h, l;
    unsigned short hh[4], ll[4];
#pragma unroll
    for (int q = 0; q < 4; q++) {
        __nv_bfloat16 hi = __float2bfloat16(f[q]);
        __nv_bfloat16 lo = __float2bfloat16(f[q] - __bfloat162float(hi));
        hh[q] = __bfloat16_as_ushort(hi);
        ll[q] = __bfloat16_as_ushort(lo);
    }
    h.x = hh[0]; h.y = hh[1]; h.z = hh[2]; h.w = hh[3];
    l.x = ll[0]; l.y = ll[1]; l.z = ll[2]; l.w = ll[3];
    *(ushort4*)((unsigned short*)gA_hi + i) = h;
    *(ushort4*)((unsigned short*)gA_lo + i) = l;
}

// ---------------------------------------------------------------------------
// Weight hi/lo convert (elementwise, keeps [K,N] layout for mma.sync B operand)
// ---------------------------------------------------------------------------
__global__ __launch_bounds__(256)
void convW_kernel(const float* __restrict__ W, int wsel)
{
    size_t i = ((size_t)blockIdx.x * 256 + threadIdx.x) * 4;
    float4 v = *(const float4*)(W + i);
    float f[4] = {v.x, v.y, v.z, v.w};
    ushort4 h, l;
    unsigned short hh[4], ll[4];
#pragma unroll
    for (int q = 0; q < 4; q++) {
        __nv_bfloat16 hi = __float2bfloat16(f[q]);
        __nv_bfloat16 lo = __float2bfloat16(f[q] - __bfloat162float(hi));
        hh[q] = __bfloat16_as_ushort(hi);
        ll[q] = __bfloat16_as_ushort(lo);
    }
    h.x = hh[0]; h.y = hh[1]; h.z = hh[2]; h.w = hh[3];
    l.x = ll[0]; l.y = ll[1]; l.z = ll[2]; l.w = ll[3];
    size_t o = (size_t)wsel * 1024 * 1024 + i;
    *(ushort4*)((unsigned short*)gW_hi + o) = h;
    *(ushort4*)((unsigned short*)gW_lo + o) = l;
}

// ---------------------------------------------------------------------------
// bf16 HMMA GEMM with hi/lo 3-term split.
// C[16384,1024] = (Ahi+Alo)[M,K] @ (Whi+Wlo)[K,N], fp32 accumulate.
// CTA tile 128x128, BK=32, 3-stage cp.async pipeline, 8 warps (32x64 each).
// ---------------------------------------------------------------------------
#define ASTRIDE 40                     // bf16 elems per A smem row (128 rows)
#define BSTRIDE 136                    // bf16 elems per B smem row (32 rows)
#define A_BYTES (128 * ASTRIDE * 2)    // 10240
#define B_BYTES (32 * BSTRIDE * 2)     // 8704
#define STAGE_BYTES (2 * A_BYTES + 2 * B_BYTES)  // 37888
#define GEMM_SMEM (3 * STAGE_BYTES)              // 113664

__device__ __forceinline__ void gemm_load_stage(
    uint32_t sb, int t, int m0, int n0, int kt,
    const __nv_bfloat16* pAh, const __nv_bfloat16* pAl,
    const __nv_bfloat16* pBh, const __nv_bfloat16* pBl)
{
    int k0 = kt * 32;
#pragma unroll
    for (int it = 0; it < 2; it++) {            // A: 128 rows x 32 cols
        int idx = t + it * 256;
        int row = idx >> 2, c8 = (idx & 3) << 3;
        size_t go = (size_t)(m0 + row) * 1024 + k0 + c8;
        uint32_t so = sb + (uint32_t)(row * ASTRIDE + c8) * 2;
        cp_async16(so, pAh + go);
        cp_async16(so + A_BYTES, pAl + go);
    }
#pragma unroll
    for (int it = 0; it < 2; it++) {            // B: 32 rows x 128 cols
        int idx = t + it * 256;
        int row = idx >> 4, c8 = (idx & 15) << 3;
        size_t go = (size_t)(k0 + row) * 1024 + n0 + c8;
        uint32_t so = sb + 2 * A_BYTES + (uint32_t)(row * BSTRIDE + c8) * 2;
        cp_async16(so, pBh + go);
        cp_async16(so + B_BYTES, pBl + go);
    }
    asm volatile("cp.async.commit_group;" ::: "memory");
}

__global__ __launch_bounds__(256, 1)
void mma_gemm_kernel(int wsel, float* __restrict__ Cext, int csel, int fmap)
{
    extern __shared__ __nv_bfloat16 smb[];
    float* C = (csel == 0) ? g_Q : (csel == 1) ? g_K : (csel == 2) ? g_V : Cext;

    const __nv_bfloat16* pAh = gA_hi;
    const __nv_bfloat16* pAl = gA_lo;
    const __nv_bfloat16* pBh = gW_hi + (size_t)wsel * 1024 * 1024;
    const __nv_bfloat16* pBl = gW_lo + (size_t)wsel * 1024 * 1024;

    int t = threadIdx.x, lane = t & 31, wid = t >> 5;
    int n0 = blockIdx.x * 128;   // N fast => A rows reused in L2 within a wave
    int m0 = blockIdx.y * 128;
    uint32_t sbase = smem_u32(smb);

    int wm = (wid >> 1) * 32;    // warp tile origin within CTA tile
    int wn = (wid & 1) * 64;

    float acc[2][8][4];
#pragma unroll
    for (int mt = 0; mt < 2; mt++)
#pragma unroll
        for (int nt = 0; nt < 8; nt++)
#pragma unroll
            for (int q = 0; q < 4; q++) acc[mt][nt][q] = 0.f;

    gemm_load_stage(sbase, t, m0, n0, 0, pAh, pAl, pBh, pBl);
    gemm_load_stage(sbase + STAGE_BYTES, t, m0, n0, 1, pAh, pAl, pBh, pBl);

    for (int kt = 0; kt < 32; kt++) {
        if (kt >= 30) asm volatile("cp.async.wait_group 0;" ::: "memory");
        else          asm volatile("cp.async.wait_group 1;" ::: "memory");
        __syncthreads();
        if (kt + 2 < 32)
            gemm_load_stage(sbase + (uint32_t)((kt + 2) % 3) * STAGE_BYTES,
                            t, m0, n0, kt + 2, pAh, pAl, pBh, pBl);

        uint32_t sb = sbase + (uint32_t)(kt % 3) * STAGE_BYTES;
#pragma unroll
        for (int ks = 0; ks < 2; ks++) {
            uint32_t aHi[2][4], aLo[2][4], bHi[16], bLo[16];
            int arow = wm + (lane & 15);
            int acol = ks * 16 + ((lane >> 4) << 3);
            uint32_t ao = sb + (uint32_t)(arow * ASTRIDE + acol) * 2;
            ldsm_x4(aHi[0], ao);
            ldsm_x4(aHi[1], ao + 16 * ASTRIDE * 2);
            ldsm_x4(aLo[0], ao + A_BYTES);
            ldsm_x4(aLo[1], ao + A_BYTES + 16 * ASTRIDE * 2);

            int brow = ks * 16 + (lane & 15);
#pragma unroll
            for (int p = 0; p < 4; p++) {
                int bcol = wn + p * 16 + ((lane >> 4) << 3);
                uint32_t bo = sb + 2 * A_BYTES + (uint32_t)(brow * BSTRIDE + bcol) * 2;
                ldsm_x4_t(&bHi[p * 4], bo);
                ldsm_x4_t(&bLo[p * 4], bo + B_BYTES);
            }
#pragma unroll
            for (int mt = 0; mt < 2; mt++)
#pragma unroll
                for (int nt = 0; nt < 8; nt++) {
                    const uint32_t* bh = &bHi[(nt >> 1) * 4 + (nt & 1) * 2];
                    const uint32_t* bl = &bLo[(nt >> 1) * 4 + (nt & 1) * 2];
                    mma16816(acc[mt][nt], aHi[mt], bh);
                    mma16816(acc[mt][nt], aHi[mt], bl);
                    mma16816(acc[mt][nt], aLo[mt], bh);
                }
        }
    }

    // Epilogue: fragment layout -> global. 4 lanes cover 8 contiguous cols (32B sectors).
    int rbase = m0 + wm + (lane >> 2);
    int cb = n0 + wn + (lane & 3) * 2;
#pragma unroll
    for (int mt = 0; mt < 2; mt++) {
        int row = rbase + mt * 16;
#pragma unroll
        for (int nt = 0; nt < 8; nt++) {
            float v0 = acc[mt][nt][0], v1 = acc[mt][nt][1];
            float v2 = acc[mt][nt][2], v3 = acc[mt][nt][3];
            if (fmap) {
                v0 = v0 > 0.f ? v0 + 1.f : expf(v0);
                v1 = v1 > 0.f ? v1 + 1.f : expf(v1);
                v2 = v2 > 0.f ? v2 + 1.f : expf(v2);
                v3 = v3 > 0.f ? v3 + 1.f : expf(v3);
            }
            float2 o0; o0.x = v0; o0.y = v1;
            float2 o1; o1.x = v2; o1.y = v3;
            *(float2*)(C + (size_t)row * 1024 + cb + nt * 8) = o0;
            *(float2*)(C + (size_t)(row + 8) * 1024 + cb + nt * 8) = o1;
        }
    }
}

// ---------------------------------------------------------------------------
// Phase A: per (b,h,chunk) local state  S_c = K_c^T V_c  (64x64), z_c = sum_t k_t
// ---------------------------------------------------------------------------
__global__ __launch_bounds__(256)
void phaseA_kernel()
{
    __shared__ float Ks[64][65];
    __shared__ float Vs[64][65];

    int blk = blockIdx.x;
    int c   = blk & (NCv - 1);
    int bh  = blk >> 5;
    int h   = bh & (Hv - 1);
    int b   = bh >> 4;
    int t   = threadIdx.x;
    int tx  = t & 15, ty = t >> 4;

    float acc[4][4];
#pragma unroll
    for (int i = 0; i < 4; i++)
#pragma unroll
        for (int j = 0; j < 4; j++) acc[i][j] = 0.f;
    float zacc = 0.f;

    size_t base = ((size_t)(b * Tv + c * Cv)) * Dv + h * HDv;

    for (int half = 0; half < 2; half++) {
        const float* Kg = g_K + base + (size_t)half * 64 * Dv;
        const float* Vg = g_V + base + (size_t)half * 64 * Dv;
        if (half) __syncthreads();
        for (int i = t; i < 64 * 16; i += 256) {
            int row = i >> 4, col4 = (i & 15) << 2;
            float4 kq = *(const float4*)(Kg + (size_t)row * Dv + col4);
            Ks[row][col4 + 0] = kq.x; Ks[row][col4 + 1] = kq.y;
            Ks[row][col4 + 2] = kq.z; Ks[row][col4 + 3] = kq.w;
            float4 vq = *(const float4*)(Vg + (size_t)row * Dv + col4);
            Vs[row][col4 + 0] = vq.x; Vs[row][col4 + 1] = vq.y;
            Vs[row][col4 + 2] = vq.z; Vs[row][col4 + 3] = vq.w;
        }
        __syncthreads();
        for (int tt = 0; tt < 64; tt++) {
            float kd[4], ve[4];
#pragma unroll
            for (int i = 0; i < 4; i++) kd[i] = Ks[tt][ty * 4 + i];
#pragma unroll
            for (int j = 0; j < 4; j++) ve[j] = Vs[tt][tx * 4 + j];
#pragma unroll
            for (int i = 0; i < 4; i++)
#pragma unroll
                for (int j = 0; j < 4; j++)
                    acc[i][j] += kd[i] * ve[j];
        }
        if (t < 64) {
            for (int tt = 0; tt < 64; tt++) zacc += Ks[tt][t];
        }
    }

    float* Sg = g_S + ((size_t)(bh * NCv + c)) * (HDv * HDv);
#pragma unroll
    for (int i = 0; i < 4; i++)
#pragma unroll
        for (int j = 0; j < 4; j++)
            Sg[(ty * 4 + i) * HDv + tx * 4 + j] = acc[i][j];
    if (t < 64) g_z[(size_t)(bh * NCv + c) * HDv + t] = zacc;
}

// ---------------------------------------------------------------------------
// Phase B: exclusive prefix over the 32 chunks (per (b,h)). 64 blocks.
// ---------------------------------------------------------------------------
__global__ __launch_bounds__(256)
void phaseB_kernel()
{
    int bh = blockIdx.x;
    int t  = threadIdx.x;

    float run[16];
#pragma unroll
    for (int r = 0; r < 16; r++) run[r] = 0.f;

    float* Sg = g_S + (size_t)bh * NCv * (HDv * HDv);
    for (int c = 0; c < NCv; c++) {
        float* p = Sg + (size_t)c * (HDv * HDv);
#pragma unroll
        for (int r = 0; r < 16; r++) {
            int idx = t + (r << 8);
            float v = p[idx];
            p[idx] = run[r];
            run[r] += v;
        }
    }
    if (t < 64) {
        float rz = 0.f;
        float* zg = g_z + (size_t)bh * NCv * HDv;
        for (int c = 0; c < NCv; c++) {
            float v = zg[c * HDv + t];
            zg[c * HDv + t] = rz;
            rz += v;
        }
    }
}

// ---------------------------------------------------------------------------
// Phase C: per (b,h,chunk) intra-chunk causal attention + carry-in state.
// ---------------------------------------------------------------------------
#define PHC_SMEM ((128*65 + 128*65 + 128*132 + 64*65 + 64 + 128) * 4)

__global__ __launch_bounds__(256)
void phaseC_kernel()
{
    extern __shared__ float smf[];
    float* Qs  = smf;
    float* KVs = Qs + 128 * 65;
    float* Asm = KVs + 128 * 65;
    float* Ssm = Asm + 128 * 132;
    float* zsm = Ssm + 64 * 65;
    float* dsm = zsm + 64;

    int blk = blockIdx.x;
    int c   = blk & (NCv - 1);
    int bh  = blk >> 5;
    int h   = bh & (Hv - 1);
    int b   = bh >> 4;
    int t   = threadIdx.x;

    size_t base = ((size_t)(b * Tv + c * Cv)) * Dv + h * HDv;
    const float* Qg = g_Q + base;
    const float* Kg = g_K + base;

    for (int i = t; i < 128 * 16; i += 256) {
        int row = i >> 4, col4 = (i & 15) << 2;
        float4 q = *(const float4*)(Qg + (size_t)row * Dv + col4);
        Qs[row * 65 + col4 + 0] = q.x; Qs[row * 65 + col4 + 1] = q.y;
        Qs[row * 65 + col4 + 2] = q.z; Qs[row * 65 + col4 + 3] = q.w;
        float4 k = *(const float4*)(Kg + (size_t)row * Dv + col4);
        KVs[row * 65 + col4 + 0] = k.x; KVs[row * 65 + col4 + 1] = k.y;
        KVs[row * 65 + col4 + 2] = k.z; KVs[row * 65 + col4 + 3] = k.w;
    }
    const float* Sg = g_S + ((size_t)(bh * NCv + c)) * (HDv * HDv);
    for (int i = t; i < HDv * HDv; i += 256)
        Ssm[(i >> 6) * 65 + (i & 63)] = Sg[i];
    if (t < 64) zsm[t] = g_z[(size_t)(bh * NCv + c) * HDv + t];
    __syncthreads();

    int tx = t & 15, ty = t >> 4;

    {
        int i0 = ty * 8, j0 = tx * 8;
        float acc[8][8];
#pragma unroll
        for (int r = 0; r < 8; r++)
#pragma unroll
            for (int s = 0; s < 8; s++) acc[r][s] = 0.f;

        for (int d = 0; d < 64; d++) {
            float qv[8], kv[8];
#pragma unroll
            for (int r = 0; r < 8; r++) qv[r] = Qs[(i0 + r) * 65 + d];
#pragma unroll
            for (int s = 0; s < 8; s++) kv[s] = KVs[(j0 + s) * 65 + d];
#pragma unroll
            for (int r = 0; r < 8; r++)
#pragma unroll
                for (int s = 0; s < 8; s++)
                    acc[r][s] += qv[r] * kv[s];
        }
#pragma unroll
        for (int r = 0; r < 8; r++)
#pragma unroll
            for (int s = 0; s < 8; s++) {
                int gi = i0 + r, gj = j0 + s;
                Asm[gi * 132 + gj] = (gj <= gi) ? acc[r][s] : 0.f;
            }
    }
    __syncthreads();

    if (t < 128) {
        float s1 = 0.f;
        for (int j = 0; j < 128; j++) s1 += Asm[t * 132 + j];
        float s2 = 0.f;
        for (int d = 0; d < 64; d++) s2 += Qs[t * 65 + d] * zsm[d];
        dsm[t] = s1 + s2 + 1e-6f;
    }

    const float* Vg = g_V + base;
    for (int i = t; i < 128 * 16; i += 256) {
        int row = i >> 4, col4 = (i & 15) << 2;
        float4 v = *(const float4*)(Vg + (size_t)row * Dv + col4);
        KVs[row * 65 + col4 + 0] = v.x; KVs[row * 65 + col4 + 1] = v.y;
        KVs[row * 65 + col4 + 2] = v.z; KVs[row * 65 + col4 + 3] = v.w;
    }
    __syncthreads();

    {
        int i0 = ty * 8, e0 = tx * 4;
        float acc[8][4];
#pragma unroll
        for (int r = 0; r < 8; r++)
#pragma unroll
            for (int e = 0; e < 4; e++) acc[r][e] = 0.f;

        for (int j = 0; j < 128; j++) {
            float vv[4];
#pragma unroll
            for (int e = 0; e < 4; e++) vv[e] = KVs[j * 65 + e0 + e];
#pragma unroll
            for (int r = 0; r < 8; r++) {
                float a = Asm[(i0 + r) * 132 + j];
#pragma unroll
                for (int e = 0; e < 4; e++) acc[r][e] += a * vv[e];
            }
        }
        for (int d = 0; d < 64; d++) {
            float sv[4];
#pragma unroll
            for (int e = 0; e < 4; e++) sv[e] = Ssm[d * 65 + e0 + e];
#pragma unroll
            for (int r = 0; r < 8; r++) {
                float q = Qs[(i0 + r) * 65 + d];
#pragma unroll
                for (int e = 0; e < 4; e++) acc[r][e] += q * sv[e];
            }
        }

        float* Yg = g_Y + base;
#pragma unroll
        for (int r = 0; r < 8; r++) {
            float inv = 1.f / dsm[i0 + r];
#pragma unroll
            for (int e = 0; e < 4; e++)
                Yg[(size_t)(i0 + r) * Dv + e0 + e] = acc[r][e] * inv;
        }
    }
}

// ---------------------------------------------------------------------------
// Launch
// ---------------------------------------------------------------------------
extern "C" void kernel_launch(void* const* d_in, const int* in_sizes, int n_in,
                              void* d_out, int out_size)
{
    const float* x  = (const float*)d_in[0];
    const float* Wq = (const float*)d_in[1];
    const float* Wk = (const float*)d_in[2];
    const float* Wv = (const float*)d_in[3];
    const float* Wo = (const float*)d_in[4];
    float* out = (float*)d_out;

    cudaFuncSetAttribute(phaseC_kernel,
                         cudaFuncAttributeMaxDynamicSharedMemorySize, PHC_SMEM);
    cudaFuncSetAttribute(mma_gemm_kernel,
                         cudaFuncAttributeMaxDynamicSharedMemorySize, GEMM_SMEM);

    convW_kernel<<<1024, 256>>>(Wq, 0);
    convW_kernel<<<1024, 256>>>(Wk, 1);
    convW_kernel<<<1024, 256>>>(Wv, 2);
    convW_kernel<<<1024, 256>>>(Wo, 3);

    convA_kernel<<<Mv * Dv / 1024, 256>>>(x, 0);

    dim3 gg(1024 / 128, Mv / 128);  // x = N blocks (fast), y = M blocks
    mma_gemm_kernel<<<gg, 256, GEMM_SMEM>>>(0, nullptr, 0, 1);  // Q = fmap(x@Wq)
    mma_gemm_kernel<<<gg, 256, GEMM_SMEM>>>(1, nullptr, 1, 1);  // K = fmap(x@Wk)
    mma_gemm_kernel<<<gg, 256, GEMM_SMEM>>>(2, nullptr, 2, 0);  // V = x@Wv

    phaseA_kernel<<<Bv * Hv * NCv, 256>>>();
    phaseB_kernel<<<Bv * Hv, 256>>>();
    phaseC_kernel<<<Bv * Hv * NCv, 256, PHC_SMEM>>>();

    convA_kernel<<<Mv * Dv / 1024, 256>>>(nullptr, 1);           // g_Y -> bf16 hi/lo
    mma_gemm_kernel<<<gg, 256, GEMM_SMEM>>>(3, out, 3, 0);       // out = Y@Wo
}

// round 4
// speedup vs baseline: 2.5307x; 1.4957x over previous
#include <cuda_runtime.h>
#include <cuda_fp16.h>
#include <math.h>
#include <stdint.h>

// Problem constants
#define Bv   4
#define Tv   4096
#define Dv   1024
#define Hv   16
#define HDv  64
#define Cv   128
#define NCv  32            // Tv / Cv
#define Mv   (Bv*Tv)       // 16384

// ---------------------------------------------------------------------------
// Scratch (device globals; no allocation allowed)
// ---------------------------------------------------------------------------
__device__ __align__(16) float g_Q[(size_t)Mv * Dv];
__device__ __align__(16) float g_K[(size_t)Mv * Dv];
__device__ __align__(16) float g_V[(size_t)Mv * Dv];
__device__ __align__(16) float g_Y[(size_t)Mv * Dv];
__device__ __align__(16) float g_S[(size_t)Bv * Hv * NCv * HDv * HDv];
__device__ __align__(16) float g_z[(size_t)Bv * Hv * NCv * HDv];

// fp16 operand buffers
__device__ __align__(16) __half gA[(size_t)Mv * Dv];            // x or Y in fp16
__device__ __align__(16) __half gW[4 * 1024 * 1024];            // [wsel][K][N] fp16

// ---------------------------------------------------------------------------
// PTX helpers (sm_80-era: mma.sync / ldmatrix / cp.async — legal on sm_100)
// ---------------------------------------------------------------------------
__device__ __forceinline__ uint32_t smem_u32(const void* p) {
    uint32_t a;
    asm("{ .reg .u64 t; cvta.to.shared.u64 t, %1; cvt.u32.u64 %0, t; }" : "=r"(a) : "l"(p));
    return a;
}

__device__ __forceinline__ void cp_async16(uint32_t saddr, const void* g) {
    asm volatile("cp.async.cg.shared.global [%0], [%1], 16;" :: "r"(saddr), "l"(g) : "memory");
}

__device__ __forceinline__ void ldsm_x4(uint32_t* r, uint32_t addr) {
    asm volatile("ldmatrix.sync.aligned.m8n8.x4.shared.b16 {%0,%1,%2,%3}, [%4];"
                 : "=r"(r[0]), "=r"(r[1]), "=r"(r[2]), "=r"(r[3]) : "r"(addr));
}
__device__ __forceinline__ void ldsm_x4_t(uint32_t* r, uint32_t addr) {
    asm volatile("ldmatrix.sync.aligned.m8n8.x4.trans.shared.b16 {%0,%1,%2,%3}, [%4];"
                 : "=r"(r[0]), "=r"(r[1]), "=r"(r[2]), "=r"(r[3]) : "r"(addr));
}

__device__ __forceinline__ void mma16816(float* c, const uint32_t* a, const uint32_t* b) {
    asm volatile(
        "mma.sync.aligned.m16n8k16.row.col.f32.f16.f16.f32 "
        "{%0,%1,%2,%3}, {%4,%5,%6,%7}, {%8,%9}, {%0,%1,%2,%3};"
        : "+f"(c[0]), "+f"(c[1]), "+f"(c[2]), "+f"(c[3])
        : "r"(a[0]), "r"(a[1]), "r"(a[2]), "r"(a[3]), "r"(b[0]), "r"(b[1]));
}

// ---------------------------------------------------------------------------
// fp32 -> fp16 conversions
// ---------------------------------------------------------------------------
__global__ __launch_bounds__(256)
void convA_kernel(const float* __restrict__ src, int asel)
{
    const float* A = asel ? g_Y : src;
    size_t i = ((size_t)blockIdx.x * 256 + threadIdx.x) * 4;
    float4 v = *(const float4*)(A + i);
    ushort4 h;
    h.x = __half_as_ushort(__float2half_rn(v.x));
    h.y = __half_as_ushort(__float2half_rn(v.y));
    h.z = __half_as_ushort(__float2half_rn(v.z));
    h.w = __half_as_ushort(__float2half_rn(v.w));
    *(ushort4*)((unsigned short*)gA + i) = h;
}

__global__ __launch_bounds__(256)
void convW_kernel(const float* __restrict__ W, int wsel)
{
    size_t i = ((size_t)blockIdx.x * 256 + threadIdx.x) * 4;
    float4 v = *(const float4*)(W + i);
    ushort4 h;
    h.x = __half_as_ushort(__float2half_rn(v.x));
    h.y = __half_as_ushort(__float2half_rn(v.y));
    h.z = __half_as_ushort(__float2half_rn(v.z));
    h.w = __half_as_ushort(__float2half_rn(v.w));
    *(ushort4*)((unsigned short*)(gW + (size_t)wsel * 1024 * 1024) + i) = h;
}

// ---------------------------------------------------------------------------
// fp16 HMMA GEMM: C[16384,1024] = A[M,K] @ W[K,N], fp32 accumulate.
// CTA tile 256x128, BK=32, 3-stage cp.async, 8 warps (64x64 warp tiles, 4x2).
// ---------------------------------------------------------------------------
#define ASTRIDE 40                       // fp16 elems per A smem row
#define BSTRIDE 136                      // fp16 elems per B smem row
#define A_SM    (256 * ASTRIDE * 2)      // 20480 bytes
#define B_SM    (32 * BSTRIDE * 2)       // 8704 bytes
#define STAGE_BYTES (A_SM + B_SM)        // 29184
#define GEMM_SMEM (3 * STAGE_BYTES)      // 87552

__device__ __forceinline__ void gemm_load_stage(
    uint32_t sb, int t, int m0, int n0, int kt,
    const __half* pA, const __half* pB)
{
    int k0 = kt * 32;
#pragma unroll
    for (int it = 0; it < 4; it++) {            // A: 256 rows x 32 cols
        int idx = t + it * 256;
        int row = idx >> 2, c8 = (idx & 3) << 3;
        cp_async16(sb + (uint32_t)(row * ASTRIDE + c8) * 2,
                   pA + (size_t)(m0 + row) * 1024 + k0 + c8);
    }
#pragma unroll
    for (int it = 0; it < 2; it++) {            // B: 32 rows x 128 cols
        int idx = t + it * 256;
        int row = idx >> 4, c8 = (idx & 15) << 3;
        cp_async16(sb + A_SM + (uint32_t)(row * BSTRIDE + c8) * 2,
                   pB + (size_t)(k0 + row) * 1024 + n0 + c8);
    }
    asm volatile("cp.async.commit_group;" ::: "memory");
}

__global__ __launch_bounds__(256, 1)
void mma_gemm_kernel(int wsel, float* __restrict__ Cext, int csel, int fmap)
{
    extern __shared__ __half smh[];
    float* C = (csel == 0) ? g_Q : (csel == 1) ? g_K : (csel == 2) ? g_V : Cext;

    const __half* pA = gA;
    const __half* pB = gW + (size_t)wsel * 1024 * 1024;

    int t = threadIdx.x, lane = t & 31, wid = t >> 5;
    int n0 = blockIdx.x * 128;   // N fast => A rows reused in L2 within a wave
    int m0 = blockIdx.y * 256;
    uint32_t sbase = smem_u32(smh);

    int wm = (wid >> 1) * 64;    // warp tile origin: 4 (m) x 2 (n)
    int wn = (wid & 1) * 64;

    float acc[4][8][4];
#pragma unroll
    for (int mi = 0; mi < 4; mi++)
#pragma unroll
        for (int nt = 0; nt < 8; nt++)
#pragma unroll
            for (int q = 0; q < 4; q++) acc[mi][nt][q] = 0.f;

    gemm_load_stage(sbase, t, m0, n0, 0, pA, pB);
    gemm_load_stage(sbase + STAGE_BYTES, t, m0, n0, 1, pA, pB);

    for (int kt = 0; kt < 32; kt++) {
        if (kt >= 30) asm volatile("cp.async.wait_group 0;" ::: "memory");
        else          asm volatile("cp.async.wait_group 1;" ::: "memory");
        __syncthreads();
        if (kt + 2 < 32)
            gemm_load_stage(sbase + (uint32_t)((kt + 2) % 3) * STAGE_BYTES,
                            t, m0, n0, kt + 2, pA, pB);

        uint32_t sb = sbase + (uint32_t)(kt % 3) * STAGE_BYTES;
#pragma unroll
        for (int ks = 0; ks < 2; ks++) {
            uint32_t aF[4][4], bF[16];
            int arow = lane & 15;
            int acol = ks * 16 + ((lane >> 4) << 3);
#pragma unroll
            for (int mi = 0; mi < 4; mi++)
                ldsm_x4(aF[mi], sb + (uint32_t)((wm + mi * 16 + arow) * ASTRIDE + acol) * 2);

            int brow = ks * 16 + (lane & 15);
#pragma unroll
            for (int p = 0; p < 4; p++) {
                int bcol = wn + p * 16 + ((lane >> 4) << 3);
                ldsm_x4_t(&bF[p * 4], sb + A_SM + (uint32_t)(brow * BSTRIDE + bcol) * 2);
            }
#pragma unroll
            for (int mi = 0; mi < 4; mi++)
#pragma unroll
                for (int nt = 0; nt < 8; nt++)
                    mma16816(acc[mi][nt], aF[mi], &bF[(nt >> 1) * 4 + (nt & 1) * 2]);
        }
    }

    // Epilogue
    int rbase = m0 + wm + (lane >> 2);
    int cb = n0 + wn + (lane & 3) * 2;
#pragma unroll
    for (int mi = 0; mi < 4; mi++) {
        int row = rbase + mi * 16;
#pragma unroll
        for (int nt = 0; nt < 8; nt++) {
            float v0 = acc[mi][nt][0], v1 = acc[mi][nt][1];
            float v2 = acc[mi][nt][2], v3 = acc[mi][nt][3];
            if (fmap) {
                v0 = v0 > 0.f ? v0 + 1.f : expf(v0);
                v1 = v1 > 0.f ? v1 + 1.f : expf(v1);
                v2 = v2 > 0.f ? v2 + 1.f : expf(v2);
                v3 = v3 > 0.f ? v3 + 1.f : expf(v3);
            }
            float2 o0; o0.x = v0; o0.y = v1;
            float2 o1; o1.x = v2; o1.y = v3;
            *(float2*)(C + (size_t)row * 1024 + cb + nt * 8) = o0;
            *(float2*)(C + (size_t)(row + 8) * 1024 + cb + nt * 8) = o1;
        }
    }
}

// ---------------------------------------------------------------------------
// Phase A: per (b,h,chunk) local state  S_c = K_c^T V_c  (64x64), z_c = sum_t k_t
// ---------------------------------------------------------------------------
__global__ __launch_bounds__(256)
void phaseA_kernel()
{
    __shared__ float Ks[64][65];
    __shared__ float Vs[64][65];

    int blk = blockIdx.x;
    int c   = blk & (NCv - 1);
    int bh  = blk >> 5;
    int h   = bh & (Hv - 1);
    int b   = bh >> 4;
    int t   = threadIdx.x;
    int tx  = t & 15, ty = t >> 4;

    float acc[4][4];
#pragma unroll
    for (int i = 0; i < 4; i++)
#pragma unroll
        for (int j = 0; j < 4; j++) acc[i][j] = 0.f;
    float zacc = 0.f;

    size_t base = ((size_t)(b * Tv + c * Cv)) * Dv + h * HDv;

    for (int half = 0; half < 2; half++) {
        const float* Kg = g_K + base + (size_t)half * 64 * Dv;
        const float* Vg = g_V + base + (size_t)half * 64 * Dv;
        if (half) __syncthreads();
        for (int i = t; i < 64 * 16; i += 256) {
            int row = i >> 4, col4 = (i & 15) << 2;
            float4 kq = *(const float4*)(Kg + (size_t)row * Dv + col4);
            Ks[row][col4 + 0] = kq.x; Ks[row][col4 + 1] = kq.y;
            Ks[row][col4 + 2] = kq.z; Ks[row][col4 + 3] = kq.w;
            float4 vq = *(const float4*)(Vg + (size_t)row * Dv + col4);
            Vs[row][col4 + 0] = vq.x; Vs[row][col4 + 1] = vq.y;
            Vs[row][col4 + 2] = vq.z; Vs[row][col4 + 3] = vq.w;
        }
        __syncthreads();
        for (int tt = 0; tt < 64; tt++) {
            float kd[4], ve[4];
#pragma unroll
            for (int i = 0; i < 4; i++) kd[i] = Ks[tt][ty * 4 + i];
#pragma unroll
            for (int j = 0; j < 4; j++) ve[j] = Vs[tt][tx * 4 + j];
#pragma unroll
            for (int i = 0; i < 4; i++)
#pragma unroll
                for (int j = 0; j < 4; j++)
                    acc[i][j] += kd[i] * ve[j];
        }
        if (t < 64) {
            for (int tt = 0; tt < 64; tt++) zacc += Ks[tt][t];
        }
    }

    float* Sg = g_S + ((size_t)(bh * NCv + c)) * (HDv * HDv);
#pragma unroll
    for (int i = 0; i < 4; i++)
#pragma unroll
        for (int j = 0; j < 4; j++)
            Sg[(ty * 4 + i) * HDv + tx * 4 + j] = acc[i][j];
    if (t < 64) g_z[(size_t)(bh * NCv + c) * HDv + t] = zacc;
}

// ---------------------------------------------------------------------------
// Phase B: exclusive prefix over the 32 chunks (per (b,h)). 64 blocks.
// ---------------------------------------------------------------------------
__global__ __launch_bounds__(256)
void phaseB_kernel()
{
    int bh = blockIdx.x;
    int t  = threadIdx.x;

    float run[16];
#pragma unroll
    for (int r = 0; r < 16; r++) run[r] = 0.f;

    float* Sg = g_S + (size_t)bh * NCv * (HDv * HDv);
    for (int c = 0; c < NCv; c++) {
        float* p = Sg + (size_t)c * (HDv * HDv);
#pragma unroll
        for (int r = 0; r < 16; r++) {
            int idx = t + (r << 8);
            float v = p[idx];
            p[idx] = run[r];
            run[r] += v;
        }
    }
    if (t < 64) {
        float rz = 0.f;
        float* zg = g_z + (size_t)bh * NCv * HDv;
        for (int c = 0; c < NCv; c++) {
            float v = zg[c * HDv + t];
            zg[c * HDv + t] = rz;
            rz += v;
        }
    }
}

// ---------------------------------------------------------------------------
// Phase C: per (b,h,chunk) intra-chunk causal attention + carry-in state.
// ---------------------------------------------------------------------------
#define PHC_SMEM ((128*65 + 128*65 + 128*132 + 64*65 + 64 + 128) * 4)

__global__ __launch_bounds__(256)
void phaseC_kernel()
{
    extern __shared__ float smf[];
    float* Qs  = smf;
    float* KVs = Qs + 128 * 65;
    float* Asm = KVs + 128 * 65;
    float* Ssm = Asm + 128 * 132;
    float* zsm = Ssm + 64 * 65;
    float* dsm = zsm + 64;

    int blk = blockIdx.x;
    int c   = blk & (NCv - 1);
    int bh  = blk >> 5;
    int h   = bh & (Hv - 1);
    int b   = bh >> 4;
    int t   = threadIdx.x;

    size_t base = ((size_t)(b * Tv + c * Cv)) * Dv + h * HDv;
    const float* Qg = g_Q + base;
    const float* Kg = g_K + base;

    for (int i = t; i < 128 * 16; i += 256) {
        int row = i >> 4, col4 = (i & 15) << 2;
        float4 q = *(const float4*)(Qg + (size_t)row * Dv + col4);
        Qs[row * 65 + col4 + 0] = q.x; Qs[row * 65 + col4 + 1] = q.y;
        Qs[row * 65 + col4 + 2] = q.z; Qs[row * 65 + col4 + 3] = q.w;
        float4 k = *(const float4*)(Kg + (size_t)row * Dv + col4);
        KVs[row * 65 + col4 + 0] = k.x; KVs[row * 65 + col4 + 1] = k.y;
        KVs[row * 65 + col4 + 2] = k.z; KVs[row * 65 + col4 + 3] = k.w;
    }
    const float* Sg = g_S + ((size_t)(bh * NCv + c)) * (HDv * HDv);
    for (int i = t; i < HDv * HDv; i += 256)
        Ssm[(i >> 6) * 65 + (i & 63)] = Sg[i];
    if (t < 64) zsm[t] = g_z[(size_t)(bh * NCv + c) * HDv + t];
    __syncthreads();

    int tx = t & 15, ty = t >> 4;

    {
        int i0 = ty * 8, j0 = tx * 8;
        float acc[8][8];
#pragma unroll
        for (int r = 0; r < 8; r++)
#pragma unroll
            for (int s = 0; s < 8; s++) acc[r][s] = 0.f;

        for (int d = 0; d < 64; d++) {
            float qv[8], kv[8];
#pragma unroll
            for (int r = 0; r < 8; r++) qv[r] = Qs[(i0 + r) * 65 + d];
#pragma unroll
            for (int s = 0; s < 8; s++) kv[s] = KVs[(j0 + s) * 65 + d];
#pragma unroll
            for (int r = 0; r < 8; r++)
#pragma unroll
                for (int s = 0; s < 8; s++)
                    acc[r][s] += qv[r] * kv[s];
        }
#pragma unroll
        for (int r = 0; r < 8; r++)
#pragma unroll
            for (int s = 0; s < 8; s++) {
                int gi = i0 + r, gj = j0 + s;
                Asm[gi * 132 + gj] = (gj <= gi) ? acc[r][s] : 0.f;
            }
    }
    __syncthreads();

    if (t < 128) {
        float s1 = 0.f;
        for (int j = 0; j < 128; j++) s1 += Asm[t * 132 + j];
        float s2 = 0.f;
        for (int d = 0; d < 64; d++) s2 += Qs[t * 65 + d] * zsm[d];
        dsm[t] = s1 + s2 + 1e-6f;
    }

    const float* Vg = g_V + base;
    for (int i = t; i < 128 * 16; i += 256) {
        int row = i >> 4, col4 = (i & 15) << 2;
        float4 v = *(const float4*)(Vg + (size_t)row * Dv + col4);
        KVs[row * 65 + col4 + 0] = v.x; KVs[row * 65 + col4 + 1] = v.y;
        KVs[row * 65 + col4 + 2] = v.z; KVs[row * 65 + col4 + 3] = v.w;
    }
    __syncthreads();

    {
        int i0 = ty * 8, e0 = tx * 4;
        float acc[8][4];
#pragma unroll
        for (int r = 0; r < 8; r++)
#pragma unroll
            for (int e = 0; e < 4; e++) acc[r][e] = 0.f;

        for (int j = 0; j < 128; j++) {
            float vv[4];
#pragma unroll
            for (int e = 0; e < 4; e++) vv[e] = KVs[j * 65 + e0 + e];
#pragma unroll
            for (int r = 0; r < 8; r++) {
                float a = Asm[(i0 + r) * 132 + j];
#pragma unroll
                for (int e = 0; e < 4; e++) acc[r][e] += a * vv[e];
            }
        }
        for (int d = 0; d < 64; d++) {
            float sv[4];
#pragma unroll
            for (int e = 0; e < 4; e++) sv[e] = Ssm[d * 65 + e0 + e];
#pragma unroll
            for (int r = 0; r < 8; r++) {
                float q = Qs[(i0 + r) * 65 + d];
#pragma unroll
                for (int e = 0; e < 4; e++) acc[r][e] += q * sv[e];
            }
        }

        float* Yg = g_Y + base;
#pragma unroll
        for (int r = 0; r < 8; r++) {
            float inv = 1.f / dsm[i0 + r];
#pragma unroll
            for (int e = 0; e < 4; e++)
                Yg[(size_t)(i0 + r) * Dv + e0 + e] = acc[r][e] * inv;
        }
    }
}

// ---------------------------------------------------------------------------
// Launch
// ---------------------------------------------------------------------------
extern "C" void kernel_launch(void* const* d_in, const int* in_sizes, int n_in,
                              void* d_out, int out_size)
{
    const float* x  = (const float*)d_in[0];
    const float* Wq = (const float*)d_in[1];
    const float* Wk = (const float*)d_in[2];
    const float* Wv = (const float*)d_in[3];
    const float* Wo = (const float*)d_in[4];
    float* out = (float*)d_out;

    cudaFuncSetAttribute(phaseC_kernel,
                         cudaFuncAttributeMaxDynamicSharedMemorySize, PHC_SMEM);
    cudaFuncSetAttribute(mma_gemm_kernel,
                         cudaFuncAttributeMaxDynamicSharedMemorySize, GEMM_SMEM);

    convW_kernel<<<1024, 256>>>(Wq, 0);
    convW_kernel<<<1024, 256>>>(Wk, 1);
    convW_kernel<<<1024, 256>>>(Wv, 2);
    convW_kernel<<<1024, 256>>>(Wo, 3);

    convA_kernel<<<Mv * Dv / 1024, 256>>>(x, 0);

    dim3 gg(1024 / 128, Mv / 256);  // x = N blocks (fast), y = M blocks
    mma_gemm_kernel<<<gg, 256, GEMM_SMEM>>>(0, nullptr, 0, 1);  // Q = fmap(x@Wq)
    mma_gemm_kernel<<<gg, 256, GEMM_SMEM>>>(1, nullptr, 1, 1);  // K = fmap(x@Wk)
    mma_gemm_kernel<<<gg, 256, GEMM_SMEM>>>(2, nullptr, 2, 0);  // V = x@Wv

    phaseA_kernel<<<Bv * Hv * NCv, 256>>>();
    phaseB_kernel<<<Bv * Hv, 256>>>();
    phaseC_kernel<<<Bv * Hv * NCv, 256, PHC_SMEM>>>();

    convA_kernel<<<Mv * Dv / 1024, 256>>>(nullptr, 1);           // g_Y -> fp16
    mma_gemm_kernel<<<gg, 256, GEMM_SMEM>>>(3, out, 3, 0);       // out = Y@Wo
}

// round 5
// speedup vs baseline: 2.9402x; 1.1618x over previous
#include <cuda_runtime.h>
#include <cuda_fp16.h>
#include <math.h>
#include <stdint.h>

// Problem constants
#define Bv   4
#define Tv   4096
#define Dv   1024
#define Hv   16
#define HDv  64
#define Cv   128
#define NCv  32            // Tv / Cv
#define Mv   (Bv*Tv)       // 16384

// ---------------------------------------------------------------------------
// Scratch (device globals; no allocation allowed)
// ---------------------------------------------------------------------------
__device__ __align__(16) float g_Q[(size_t)Mv * Dv];
__device__ __align__(16) float g_K[(size_t)Mv * Dv];
__device__ __align__(16) float g_V[(size_t)Mv * Dv];
__device__ __align__(16) float g_S[(size_t)Bv * Hv * NCv * HDv * HDv];
__device__ __align__(16) float g_z[(size_t)Bv * Hv * NCv * HDv];

// fp16 operand buffers
__device__ __align__(16) __half gA[(size_t)Mv * Dv];   // x (QKV GEMMs), then Y (Wo GEMM)
__device__ __align__(16) __half gW[4 * 1024 * 1024];   // [wsel][K][N] fp16

// ---------------------------------------------------------------------------
// PTX helpers
// ---------------------------------------------------------------------------
__device__ __forceinline__ uint32_t smem_u32(const void* p) {
    uint32_t a;
    asm("{ .reg .u64 t; cvta.to.shared.u64 t, %1; cvt.u32.u64 %0, t; }" : "=r"(a) : "l"(p));
    return a;
}

__device__ __forceinline__ void cp_async16(uint32_t saddr, const void* g) {
    asm volatile("cp.async.cg.shared.global [%0], [%1], 16;" :: "r"(saddr), "l"(g) : "memory");
}

__device__ __forceinline__ void ldsm_x4(uint32_t* r, uint32_t addr) {
    asm volatile("ldmatrix.sync.aligned.m8n8.x4.shared.b16 {%0,%1,%2,%3}, [%4];"
                 : "=r"(r[0]), "=r"(r[1]), "=r"(r[2]), "=r"(r[3]) : "r"(addr));
}
__device__ __forceinline__ void ldsm_x4_t(uint32_t* r, uint32_t addr) {
    asm volatile("ldmatrix.sync.aligned.m8n8.x4.trans.shared.b16 {%0,%1,%2,%3}, [%4];"
                 : "=r"(r[0]), "=r"(r[1]), "=r"(r[2]), "=r"(r[3]) : "r"(addr));
}

__device__ __forceinline__ void mma16816(float* c, const uint32_t* a, const uint32_t* b) {
    asm volatile(
        "mma.sync.aligned.m16n8k16.row.col.f32.f16.f16.f32 "
        "{%0,%1,%2,%3}, {%4,%5,%6,%7}, {%8,%9}, {%0,%1,%2,%3};"
        : "+f"(c[0]), "+f"(c[1]), "+f"(c[2]), "+f"(c[3])
        : "r"(a[0]), "r"(a[1]), "r"(a[2]), "r"(a[3]), "r"(b[0]), "r"(b[1]));
}

// ---------------------------------------------------------------------------
// fp32 -> fp16 conversions
// ---------------------------------------------------------------------------
__global__ __launch_bounds__(256)
void convA_kernel(const float* __restrict__ src)
{
    size_t i = ((size_t)blockIdx.x * 256 + threadIdx.x) * 4;
    float4 v = *(const float4*)(src + i);
    ushort4 h;
    h.x = __half_as_ushort(__float2half_rn(v.x));
    h.y = __half_as_ushort(__float2half_rn(v.y));
    h.z = __half_as_ushort(__float2half_rn(v.z));
    h.w = __half_as_ushort(__float2half_rn(v.w));
    *(ushort4*)((unsigned short*)gA + i) = h;
}

__global__ __launch_bounds__(256)
void convW_kernel(const float* __restrict__ W, int wsel)
{
    size_t i = ((size_t)blockIdx.x * 256 + threadIdx.x) * 4;
    float4 v = *(const float4*)(W + i);
    ushort4 h;
    h.x = __half_as_ushort(__float2half_rn(v.x));
    h.y = __half_as_ushort(__float2half_rn(v.y));
    h.z = __half_as_ushort(__float2half_rn(v.z));
    h.w = __half_as_ushort(__float2half_rn(v.w));
    *(ushort4*)((unsigned short*)(gW + (size_t)wsel * 1024 * 1024) + i) = h;
}

// ---------------------------------------------------------------------------
// fp16 HMMA GEMM: C[16384,1024] = A[M,K] @ W[K,N], fp32 accumulate.
// CTA tile 128x128, BK=32, 3-stage cp.async, 4 warps (64x64 warp tiles, 2x2),
// 128 threads => 2 CTAs per SM (hide syncthreads/wait bubbles cross-CTA).
// wsel < 0: use blockIdx.z for wsel/csel/fmap (fused QKV launch).
// ---------------------------------------------------------------------------
#define ASTRIDE 40                       // fp16 elems per A smem row
#define BSTRIDE 136                      // fp16 elems per B smem row
#define A_SM    (128 * ASTRIDE * 2)      // 10240 bytes
#define B_SM    (32 * BSTRIDE * 2)       // 8704 bytes
#define STAGE_BYTES (A_SM + B_SM)        // 18944
#define GEMM_SMEM (3 * STAGE_BYTES)      // 56832

__device__ __forceinline__ void gemm_load_stage(
    uint32_t sb, int t, int m0, int n0, int kt,
    const __half* pA, const __half* pB)
{
    int k0 = kt * 32;
#pragma unroll
    for (int it = 0; it < 4; it++) {            // A: 128 rows x 32 cols
        int idx = t + it * 128;
        int row = idx >> 2, c8 = (idx & 3) << 3;
        cp_async16(sb + (uint32_t)(row * ASTRIDE + c8) * 2,
                   pA + (size_t)(m0 + row) * 1024 + k0 + c8);
    }
#pragma unroll
    for (int it = 0; it < 4; it++) {            // B: 32 rows x 128 cols
        int idx = t + it * 128;
        int row = idx >> 4, c8 = (idx & 15) << 3;
        cp_async16(sb + A_SM + (uint32_t)(row * BSTRIDE + c8) * 2,
                   pB + (size_t)(k0 + row) * 1024 + n0 + c8);
    }
    asm volatile("cp.async.commit_group;" ::: "memory");
}

__global__ __launch_bounds__(128, 2)
void mma_gemm_kernel(int wsel, float* __restrict__ Cext, int csel, int fmap)
{
    extern __shared__ __half smh[];
    if (wsel < 0) { wsel = blockIdx.z; csel = blockIdx.z; fmap = (blockIdx.z < 2); }
    float* C = (csel == 0) ? g_Q : (csel == 1) ? g_K : (csel == 2) ? g_V : Cext;

    const __half* pA = gA;
    const __half* pB = gW + (size_t)wsel * 1024 * 1024;

    int t = threadIdx.x, lane = t & 31, wid = t >> 5;
    int n0 = blockIdx.x * 128;   // N fast => A rows reused in L2 within a wave
    int m0 = blockIdx.y * 128;
    uint32_t sbase = smem_u32(smh);

    int wm = (wid >> 1) * 64;    // warp tile origin: 2 (m) x 2 (n)
    int wn = (wid & 1) * 64;

    float acc[4][8][4];
#pragma unroll
    for (int mi = 0; mi < 4; mi++)
#pragma unroll
        for (int nt = 0; nt < 8; nt++)
#pragma unroll
            for (int q = 0; q < 4; q++) acc[mi][nt][q] = 0.f;

    gemm_load_stage(sbase, t, m0, n0, 0, pA, pB);
    gemm_load_stage(sbase + STAGE_BYTES, t, m0, n0, 1, pA, pB);

    for (int kt = 0; kt < 32; kt++) {
        if (kt >= 30) asm volatile("cp.async.wait_group 0;" ::: "memory");
        else          asm volatile("cp.async.wait_group 1;" ::: "memory");
        __syncthreads();
        if (kt + 2 < 32)
            gemm_load_stage(sbase + (uint32_t)((kt + 2) % 3) * STAGE_BYTES,
                            t, m0, n0, kt + 2, pA, pB);

        uint32_t sb = sbase + (uint32_t)(kt % 3) * STAGE_BYTES;
#pragma unroll
        for (int ks = 0; ks < 2; ks++) {
            uint32_t aF[4][4], bF[16];
            int arow = lane & 15;
            int acol = ks * 16 + ((lane >> 4) << 3);
#pragma unroll
            for (int mi = 0; mi < 4; mi++)
                ldsm_x4(aF[mi], sb + (uint32_t)((wm + mi * 16 + arow) * ASTRIDE + acol) * 2);

            int brow = ks * 16 + (lane & 15);
#pragma unroll
            for (int p = 0; p < 4; p++) {
                int bcol = wn + p * 16 + ((lane >> 4) << 3);
                ldsm_x4_t(&bF[p * 4], sb + A_SM + (uint32_t)(brow * BSTRIDE + bcol) * 2);
            }
#pragma unroll
            for (int mi = 0; mi < 4; mi++)
#pragma unroll
                for (int nt = 0; nt < 8; nt++)
                    mma16816(acc[mi][nt], aF[mi], &bF[(nt >> 1) * 4 + (nt & 1) * 2]);
        }
    }

    // Epilogue
    int rbase = m0 + wm + (lane >> 2);
    int cb = n0 + wn + (lane & 3) * 2;
#pragma unroll
    for (int mi = 0; mi < 4; mi++) {
        int row = rbase + mi * 16;
#pragma unroll
        for (int nt = 0; nt < 8; nt++) {
            float v0 = acc[mi][nt][0], v1 = acc[mi][nt][1];
            float v2 = acc[mi][nt][2], v3 = acc[mi][nt][3];
            if (fmap) {
                v0 = v0 > 0.f ? v0 + 1.f : expf(v0);
                v1 = v1 > 0.f ? v1 + 1.f : expf(v1);
                v2 = v2 > 0.f ? v2 + 1.f : expf(v2);
                v3 = v3 > 0.f ? v3 + 1.f : expf(v3);
            }
            float2 o0; o0.x = v0; o0.y = v1;
            float2 o1; o1.x = v2; o1.y = v3;
            *(float2*)(C + (size_t)row * 1024 + cb + nt * 8) = o0;
            *(float2*)(C + (size_t)(row + 8) * 1024 + cb + nt * 8) = o1;
        }
    }
}

// ---------------------------------------------------------------------------
// Phase A: per (b,h,chunk) local state  S_c = K_c^T V_c  (64x64), z_c = sum_t k_t
// ---------------------------------------------------------------------------
__global__ __launch_bounds__(256)
void phaseA_kernel()
{
    __shared__ float Ks[64][65];
    __shared__ float Vs[64][65];

    int blk = blockIdx.x;
    int c   = blk & (NCv - 1);
    int bh  = blk >> 5;
    int h   = bh & (Hv - 1);
    int b   = bh >> 4;
    int t   = threadIdx.x;
    int tx  = t & 15, ty = t >> 4;

    float acc[4][4];
#pragma unroll
    for (int i = 0; i < 4; i++)
#pragma unroll
        for (int j = 0; j < 4; j++) acc[i][j] = 0.f;
    float zacc = 0.f;

    size_t base = ((size_t)(b * Tv + c * Cv)) * Dv + h * HDv;

    for (int half = 0; half < 2; half++) {
        const float* Kg = g_K + base + (size_t)half * 64 * Dv;
        const float* Vg = g_V + base + (size_t)half * 64 * Dv;
        if (half) __syncthreads();
        for (int i = t; i < 64 * 16; i += 256) {
            int row = i >> 4, col4 = (i & 15) << 2;
            float4 kq = *(const float4*)(Kg + (size_t)row * Dv + col4);
            Ks[row][col4 + 0] = kq.x; Ks[row][col4 + 1] = kq.y;
            Ks[row][col4 + 2] = kq.z; Ks[row][col4 + 3] = kq.w;
            float4 vq = *(const float4*)(Vg + (size_t)row * Dv + col4);
            Vs[row][col4 + 0] = vq.x; Vs[row][col4 + 1] = vq.y;
            Vs[row][col4 + 2] = vq.z; Vs[row][col4 + 3] = vq.w;
        }
        __syncthreads();
        for (int tt = 0; tt < 64; tt++) {
            float kd[4], ve[4];
#pragma unroll
            for (int i = 0; i < 4; i++) kd[i] = Ks[tt][ty * 4 + i];
#pragma unroll
            for (int j = 0; j < 4; j++) ve[j] = Vs[tt][tx * 4 + j];
#pragma unroll
            for (int i = 0; i < 4; i++)
#pragma unroll
                for (int j = 0; j < 4; j++)
                    acc[i][j] += kd[i] * ve[j];
        }
        if (t < 64) {
            for (int tt = 0; tt < 64; tt++) zacc += Ks[tt][t];
        }
    }

    float* Sg = g_S + ((size_t)(bh * NCv + c)) * (HDv * HDv);
#pragma unroll
    for (int i = 0; i < 4; i++)
#pragma unroll
        for (int j = 0; j < 4; j++)
            Sg[(ty * 4 + i) * HDv + tx * 4 + j] = acc[i][j];
    if (t < 64) g_z[(size_t)(bh * NCv + c) * HDv + t] = zacc;
}

// ---------------------------------------------------------------------------
// Phase B: exclusive prefix over the 32 chunks (per (b,h)). 64 blocks.
// ---------------------------------------------------------------------------
__global__ __launch_bounds__(256)
void phaseB_kernel()
{
    int bh = blockIdx.x;
    int t  = threadIdx.x;

    float run[16];
#pragma unroll
    for (int r = 0; r < 16; r++) run[r] = 0.f;

    float* Sg = g_S + (size_t)bh * NCv * (HDv * HDv);
    for (int c = 0; c < NCv; c++) {
        float* p = Sg + (size_t)c * (HDv * HDv);
#pragma unroll
        for (int r = 0; r < 16; r++) {
            int idx = t + (r << 8);
            float v = p[idx];
            p[idx] = run[r];
            run[r] += v;
        }
    }
    if (t < 64) {
        float rz = 0.f;
        float* zg = g_z + (size_t)bh * NCv * HDv;
        for (int c = 0; c < NCv; c++) {
            float v = zg[c * HDv + t];
            zg[c * HDv + t] = rz;
            rz += v;
        }
    }
}

// ---------------------------------------------------------------------------
// Phase C: per (b,h,chunk) intra-chunk causal attention + carry-in state.
// Writes Y directly as fp16 into gA (consumed only by the Wo GEMM).
// ---------------------------------------------------------------------------
#define PHC_SMEM ((128*65 + 128*65 + 128*132 + 64*65 + 64 + 128) * 4)

__global__ __launch_bounds__(256)
void phaseC_kernel()
{
    extern __shared__ float smf[];
    float* Qs  = smf;
    float* KVs = Qs + 128 * 65;
    float* Asm = KVs + 128 * 65;
    float* Ssm = Asm + 128 * 132;
    float* zsm = Ssm + 64 * 65;
    float* dsm = zsm + 64;

    int blk = blockIdx.x;
    int c   = blk & (NCv - 1);
    int bh  = blk >> 5;
    int h   = bh & (Hv - 1);
    int b   = bh >> 4;
    int t   = threadIdx.x;

    size_t base = ((size_t)(b * Tv + c * Cv)) * Dv + h * HDv;
    const float* Qg = g_Q + base;
    const float* Kg = g_K + base;

    for (int i = t; i < 128 * 16; i += 256) {
        int row = i >> 4, col4 = (i & 15) << 2;
        float4 q = *(const float4*)(Qg + (size_t)row * Dv + col4);
        Qs[row * 65 + col4 + 0] = q.x; Qs[row * 65 + col4 + 1] = q.y;
        Qs[row * 65 + col4 + 2] = q.z; Qs[row * 65 + col4 + 3] = q.w;
        float4 k = *(const float4*)(Kg + (size_t)row * Dv + col4);
        KVs[row * 65 + col4 + 0] = k.x; KVs[row * 65 + col4 + 1] = k.y;
        KVs[row * 65 + col4 + 2] = k.z; KVs[row * 65 + col4 + 3] = k.w;
    }
    const float* Sg = g_S + ((size_t)(bh * NCv + c)) * (HDv * HDv);
    for (int i = t; i < HDv * HDv; i += 256)
        Ssm[(i >> 6) * 65 + (i & 63)] = Sg[i];
    if (t < 64) zsm[t] = g_z[(size_t)(bh * NCv + c) * HDv + t];
    __syncthreads();

    int tx = t & 15, ty = t >> 4;

    {
        int i0 = ty * 8, j0 = tx * 8;
        float acc[8][8];
#pragma unroll
        for (int r = 0; r < 8; r++)
#pragma unroll
            for (int s = 0; s < 8; s++) acc[r][s] = 0.f;

        for (int d = 0; d < 64; d++) {
            float qv[8], kv[8];
#pragma unroll
            for (int r = 0; r < 8; r++) qv[r] = Qs[(i0 + r) * 65 + d];
#pragma unroll
            for (int s = 0; s < 8; s++) kv[s] = KVs[(j0 + s) * 65 + d];
#pragma unroll
            for (int r = 0; r < 8; r++)
#pragma unroll
                for (int s = 0; s < 8; s++)
                    acc[r][s] += qv[r] * kv[s];
        }
#pragma unroll
        for (int r = 0; r < 8; r++)
#pragma unroll
            for (int s = 0; s < 8; s++) {
                int gi = i0 + r, gj = j0 + s;
                Asm[gi * 132 + gj] = (gj <= gi) ? acc[r][s] : 0.f;
            }
    }
    __syncthreads();

    if (t < 128) {
        float s1 = 0.f;
        for (int j = 0; j < 128; j++) s1 += Asm[t * 132 + j];
        float s2 = 0.f;
        for (int d = 0; d < 64; d++) s2 += Qs[t * 65 + d] * zsm[d];
        dsm[t] = s1 + s2 + 1e-6f;
    }

    const float* Vg = g_V + base;
    for (int i = t; i < 128 * 16; i += 256) {
        int row = i >> 4, col4 = (i & 15) << 2;
        float4 v = *(const float4*)(Vg + (size_t)row * Dv + col4);
        KVs[row * 65 + col4 + 0] = v.x; KVs[row * 65 + col4 + 1] = v.y;
        KVs[row * 65 + col4 + 2] = v.z; KVs[row * 65 + col4 + 3] = v.w;
    }
    __syncthreads();

    {
        int i0 = ty * 8, e0 = tx * 4;
        float acc[8][4];
#pragma unroll
        for (int r = 0; r < 8; r++)
#pragma unroll
            for (int e = 0; e < 4; e++) acc[r][e] = 0.f;

        for (int j = 0; j < 128; j++) {
            float vv[4];
#pragma unroll
            for (int e = 0; e < 4; e++) vv[e] = KVs[j * 65 + e0 + e];
#pragma unroll
            for (int r = 0; r < 8; r++) {
                float a = Asm[(i0 + r) * 132 + j];
#pragma unroll
                for (int e = 0; e < 4; e++) acc[r][e] += a * vv[e];
            }
        }
        for (int d = 0; d < 64; d++) {
            float sv[4];
#pragma unroll
            for (int e = 0; e < 4; e++) sv[e] = Ssm[d * 65 + e0 + e];
#pragma unroll
            for (int r = 0; r < 8; r++) {
                float q = Qs[(i0 + r) * 65 + d];
#pragma unroll
                for (int e = 0; e < 4; e++) acc[r][e] += q * sv[e];
            }
        }

        __half* Yg = gA + base;
#pragma unroll
        for (int r = 0; r < 8; r++) {
            float inv = 1.f / dsm[i0 + r];
            ushort4 o;
            o.x = __half_as_ushort(__float2half_rn(acc[r][0] * inv));
            o.y = __half_as_ushort(__float2half_rn(acc[r][1] * inv));
            o.z = __half_as_ushort(__float2half_rn(acc[r][2] * inv));
            o.w = __half_as_ushort(__float2half_rn(acc[r][3] * inv));
            *(ushort4*)((unsigned short*)Yg + (size_t)(i0 + r) * Dv + e0) = o;
        }
    }
}

// ---------------------------------------------------------------------------
// Launch
// ---------------------------------------------------------------------------
extern "C" void kernel_launch(void* const* d_in, const int* in_sizes, int n_in,
                              void* d_out, int out_size)
{
    const float* x  = (const float*)d_in[0];
    const float* Wq = (const float*)d_in[1];
    const float* Wk = (const float*)d_in[2];
    const float* Wv = (const float*)d_in[3];
    const float* Wo = (const float*)d_in[4];
    float* out = (float*)d_out;

    cudaFuncSetAttribute(phaseC_kernel,
                         cudaFuncAttributeMaxDynamicSharedMemorySize, PHC_SMEM);
    cudaFuncSetAttribute(mma_gemm_kernel,
                         cudaFuncAttributeMaxDynamicSharedMemorySize, GEMM_SMEM);

    convW_kernel<<<1024, 256>>>(Wq, 0);
    convW_kernel<<<1024, 256>>>(Wk, 1);
    convW_kernel<<<1024, 256>>>(Wv, 2);
    convW_kernel<<<1024, 256>>>(Wo, 3);

    convA_kernel<<<Mv * Dv / 1024, 256>>>(x);

    dim3 gqkv(1024 / 128, Mv / 128, 3);  // x = N blocks (fast), y = M blocks, z = Q/K/V
    mma_gemm_kernel<<<gqkv, 128, GEMM_SMEM>>>(-1, nullptr, 0, 0);

    phaseA_kernel<<<Bv * Hv * NCv, 256>>>();
    phaseB_kernel<<<Bv * Hv, 256>>>();
    phaseC_kernel<<<Bv * Hv * NCv, 256, PHC_SMEM>>>();   // writes fp16 Y into gA

    dim3 go(1024 / 128, Mv / 128);
    mma_gemm_kernel<<<go, 128, GEMM_SMEM>>>(3, out, 3, 0);  // out = Y@Wo
}

// round 6
// speedup vs baseline: 5.3646x; 1.8246x over previous
#include <cuda_runtime.h>
#include <cuda_fp16.h>
#include <math.h>
#include <stdint.h>

// Problem constants
#define Bv   4
#define Tv   4096
#define Dv   1024
#define Hv   16
#define HDv  64
#define Cv   128
#define NCv  32            // Tv / Cv
#define Mv   (Bv*Tv)       // 16384

// ---------------------------------------------------------------------------
// Scratch (device globals; no allocation allowed)
// ---------------------------------------------------------------------------
__device__ __align__(16) float g_S[(size_t)Bv * Hv * NCv * HDv * HDv];
__device__ __align__(16) float g_z[(size_t)Bv * Hv * NCv * HDv];

__device__ __align__(16) __half gA[(size_t)Mv * Dv];   // x (QKV GEMMs), then Y (Wo GEMM)
__device__ __align__(16) __half gW[4 * 1024 * 1024];   // [wsel][K][N] fp16
__device__ __align__(16) __half g_Qh[(size_t)Mv * Dv]; // feature-mapped Q (fp16)
__device__ __align__(16) __half g_Kh[(size_t)Mv * Dv]; // feature-mapped K (fp16)
__device__ __align__(16) __half g_Vh[(size_t)Mv * Dv]; // V (fp16)

// ---------------------------------------------------------------------------
// PTX helpers
// ---------------------------------------------------------------------------
__device__ __forceinline__ uint32_t smem_u32(const void* p) {
    uint32_t a;
    asm("{ .reg .u64 t; cvta.to.shared.u64 t, %1; cvt.u32.u64 %0, t; }" : "=r"(a) : "l"(p));
    return a;
}

__device__ __forceinline__ void cp_async16(uint32_t saddr, const void* g) {
    asm volatile("cp.async.cg.shared.global [%0], [%1], 16;" :: "r"(saddr), "l"(g) : "memory");
}

__device__ __forceinline__ void ldsm_x4(uint32_t* r, uint32_t addr) {
    asm volatile("ldmatrix.sync.aligned.m8n8.x4.shared.b16 {%0,%1,%2,%3}, [%4];"
                 : "=r"(r[0]), "=r"(r[1]), "=r"(r[2]), "=r"(r[3]) : "r"(addr));
}
__device__ __forceinline__ void ldsm_x4_t(uint32_t* r, uint32_t addr) {
    asm volatile("ldmatrix.sync.aligned.m8n8.x4.trans.shared.b16 {%0,%1,%2,%3}, [%4];"
                 : "=r"(r[0]), "=r"(r[1]), "=r"(r[2]), "=r"(r[3]) : "r"(addr));
}

__device__ __forceinline__ void mma16816(float* c, const uint32_t* a, uint32_t b0, uint32_t b1) {
    asm volatile(
        "mma.sync.aligned.m16n8k16.row.col.f32.f16.f16.f32 "
        "{%0,%1,%2,%3}, {%4,%5,%6,%7}, {%8,%9}, {%0,%1,%2,%3};"
        : "+f"(c[0]), "+f"(c[1]), "+f"(c[2]), "+f"(c[3])
        : "r"(a[0]), "r"(a[1]), "r"(a[2]), "r"(a[3]), "r"(b0), "r"(b1));
}

__device__ __forceinline__ uint32_t pack_h2(float lo, float hi) {
    __half2 h = __floats2half2_rn(lo, hi);   // x = lo (low 16 bits), y = hi
    return *(uint32_t*)&h;
}

// ---------------------------------------------------------------------------
// fp32 -> fp16 conversions
// ---------------------------------------------------------------------------
__global__ __launch_bounds__(256)
void convA_kernel(const float* __restrict__ src)
{
    size_t i = ((size_t)blockIdx.x * 256 + threadIdx.x) * 4;
    float4 v = *(const float4*)(src + i);
    ushort4 h;
    h.x = __half_as_ushort(__float2half_rn(v.x));
    h.y = __half_as_ushort(__float2half_rn(v.y));
    h.z = __half_as_ushort(__float2half_rn(v.z));
    h.w = __half_as_ushort(__float2half_rn(v.w));
    *(ushort4*)((unsigned short*)gA + i) = h;
}

__global__ __launch_bounds__(256)
void convW_kernel(const float* __restrict__ W, int wsel)
{
    size_t i = ((size_t)blockIdx.x * 256 + threadIdx.x) * 4;
    float4 v = *(const float4*)(W + i);
    ushort4 h;
    h.x = __half_as_ushort(__float2half_rn(v.x));
    h.y = __half_as_ushort(__float2half_rn(v.y));
    h.z = __half_as_ushort(__float2half_rn(v.z));
    h.w = __half_as_ushort(__float2half_rn(v.w));
    *(ushort4*)((unsigned short*)(gW + (size_t)wsel * 1024 * 1024) + i) = h;
}

// ---------------------------------------------------------------------------
// fp16 HMMA GEMM: C = A[M,K] @ W[K,N]. CTA 128x128, BK=32, 4-stage cp.async,
// 4 warps (64x64 warp tiles), 2 CTAs/SM. csel 0/1/2 -> fp16 Q/K/V, 3 -> fp32 out.
// ---------------------------------------------------------------------------
#define ASTRIDE 40
#define BSTRIDE 136
#define A_SM    (128 * ASTRIDE * 2)      // 10240
#define B_SM    (32 * BSTRIDE * 2)       // 8704
#define STAGE_BYTES (A_SM + B_SM)        // 18944
#define GEMM_SMEM (4 * STAGE_BYTES)      // 75776

__device__ __forceinline__ void gemm_load_stage(
    uint32_t sb, int t, int m0, int n0, int kt,
    const __half* pA, const __half* pB)
{
    int k0 = kt * 32;
#pragma unroll
    for (int it = 0; it < 4; it++) {
        int idx = t + it * 128;
        int row = idx >> 2, c8 = (idx & 3) << 3;
        cp_async16(sb + (uint32_t)(row * ASTRIDE + c8) * 2,
                   pA + (size_t)(m0 + row) * 1024 + k0 + c8);
    }
#pragma unroll
    for (int it = 0; it < 4; it++) {
        int idx = t + it * 128;
        int row = idx >> 4, c8 = (idx & 15) << 3;
        cp_async16(sb + A_SM + (uint32_t)(row * BSTRIDE + c8) * 2,
                   pB + (size_t)(k0 + row) * 1024 + n0 + c8);
    }
    asm volatile("cp.async.commit_group;" ::: "memory");
}

__global__ __launch_bounds__(128, 2)
void mma_gemm_kernel(int wsel, float* __restrict__ Cext, int csel, int fmap)
{
    extern __shared__ __half smh[];
    if (wsel < 0) { wsel = blockIdx.z; csel = blockIdx.z; fmap = (blockIdx.z < 2); }

    const __half* pA = gA;
    const __half* pB = gW + (size_t)wsel * 1024 * 1024;

    int t = threadIdx.x, lane = t & 31, wid = t >> 5;
    int n0 = blockIdx.x * 128;
    int m0 = blockIdx.y * 128;
    uint32_t sbase = smem_u32(smh);

    int wm = (wid >> 1) * 64;
    int wn = (wid & 1) * 64;

    float acc[4][8][4];
#pragma unroll
    for (int mi = 0; mi < 4; mi++)
#pragma unroll
        for (int nt = 0; nt < 8; nt++)
#pragma unroll
            for (int q = 0; q < 4; q++) acc[mi][nt][q] = 0.f;

    gemm_load_stage(sbase, t, m0, n0, 0, pA, pB);
    gemm_load_stage(sbase + STAGE_BYTES, t, m0, n0, 1, pA, pB);
    gemm_load_stage(sbase + 2 * STAGE_BYTES, t, m0, n0, 2, pA, pB);

    for (int kt = 0; kt < 32; kt++) {
        if (kt <= 29)      asm volatile("cp.async.wait_group 2;" ::: "memory");
        else if (kt == 30) asm volatile("cp.async.wait_group 1;" ::: "memory");
        else               asm volatile("cp.async.wait_group 0;" ::: "memory");
        __syncthreads();
        if (kt + 3 < 32)
            gemm_load_stage(sbase + (uint32_t)((kt + 3) & 3) * STAGE_BYTES,
                            t, m0, n0, kt + 3, pA, pB);

        uint32_t sb = sbase + (uint32_t)(kt & 3) * STAGE_BYTES;
#pragma unroll
        for (int ks = 0; ks < 2; ks++) {
            uint32_t aF[4][4], bF[16];
            int arow = lane & 15;
            int acol = ks * 16 + ((lane >> 4) << 3);
#pragma unroll
            for (int mi = 0; mi < 4; mi++)
                ldsm_x4(aF[mi], sb + (uint32_t)((wm + mi * 16 + arow) * ASTRIDE + acol) * 2);

            int brow = ks * 16 + (lane & 15);
#pragma unroll
            for (int p = 0; p < 4; p++) {
                int bcol = wn + p * 16 + ((lane >> 4) << 3);
                ldsm_x4_t(&bF[p * 4], sb + A_SM + (uint32_t)(brow * BSTRIDE + bcol) * 2);
            }
#pragma unroll
            for (int mi = 0; mi < 4; mi++)
#pragma unroll
                for (int nt = 0; nt < 8; nt++)
                    mma16816(acc[mi][nt], aF[mi],
                             bF[(nt >> 1) * 4 + (nt & 1) * 2], bF[(nt >> 1) * 4 + (nt & 1) * 2 + 1]);
        }
    }

    int rbase = m0 + wm + (lane >> 2);
    int cb0 = wn + (lane & 3) * 2;
#pragma unroll
    for (int mi = 0; mi < 4; mi++) {
        int row = rbase + mi * 16;
#pragma unroll
        for (int nt = 0; nt < 8; nt++) {
            float v0 = acc[mi][nt][0], v1 = acc[mi][nt][1];
            float v2 = acc[mi][nt][2], v3 = acc[mi][nt][3];
            if (fmap) {
                v0 = v0 > 0.f ? v0 + 1.f : expf(v0);
                v1 = v1 > 0.f ? v1 + 1.f : expf(v1);
                v2 = v2 > 0.f ? v2 + 1.f : expf(v2);
                v3 = v3 > 0.f ? v3 + 1.f : expf(v3);
            }
            if (csel < 3) {
                __half* Ch = (csel == 0) ? g_Qh : (csel == 1) ? g_Kh : g_Vh;
                uint32_t p0 = pack_h2(v0, v1);
                uint32_t p1 = pack_h2(v2, v3);
                *(uint32_t*)((unsigned short*)Ch + (size_t)row * 1024 + n0 + cb0 + nt * 8) = p0;
                *(uint32_t*)((unsigned short*)Ch + (size_t)(row + 8) * 1024 + n0 + cb0 + nt * 8) = p1;
            } else {
                float2 o0; o0.x = v0; o0.y = v1;
                float2 o1; o1.x = v2; o1.y = v3;
                *(float2*)(Cext + (size_t)row * 1024 + n0 + cb0 + nt * 8) = o0;
                *(float2*)(Cext + (size_t)(row + 8) * 1024 + n0 + cb0 + nt * 8) = o1;
            }
        }
    }
}

// ---------------------------------------------------------------------------
// Phase A (tensor): S_c = K_c^T V_c (64x64 fp32), z_c = col sums of K.
// 128 threads / 4 warps, warp handles 16 d-rows, k = t (128) in 8 ksteps.
// ---------------------------------------------------------------------------
#define KT_STRIDE 136   // Kt[64][136] halves ([d][t] transposed)
#define VA_STRIDE 72    // Vs[128][72]

__global__ __launch_bounds__(128)
void phaseA_kernel()
{
    __shared__ __half Kt[64 * KT_STRIDE];
    __shared__ __half Vs[128 * VA_STRIDE];

    int blk = blockIdx.x;
    int c   = blk & (NCv - 1);
    int bh  = blk >> 5;
    int h   = bh & (Hv - 1);
    int b   = bh >> 4;
    int t   = threadIdx.x;
    int lane = t & 31, wid = t >> 5;

    size_t base = ((size_t)(b * Tv + c * Cv)) * Dv + h * HDv;

    // Load K transposed ([t][d] -> Kt[d][t]) and V ([t][e] -> Vs, padded)
    for (int idx = t; idx < 128 * 8; idx += 128) {
        int row = idx >> 3, c8 = (idx & 7) << 3;
        ushort4 kq = *(const ushort4*)((const unsigned short*)g_Kh + base + (size_t)row * Dv + c8);
        unsigned short kk[8] = {kq.x, kq.y, kq.z, kq.w, 0, 0, 0, 0};
        ushort4 kq2 = *(const ushort4*)((const unsigned short*)g_Kh + base + (size_t)row * Dv + c8 + 4);
        kk[4] = kq2.x; kk[5] = kq2.y; kk[6] = kq2.z; kk[7] = kq2.w;
#pragma unroll
        for (int q = 0; q < 8; q++)
            Kt[(c8 + q) * KT_STRIDE + row] = __ushort_as_half(kk[q]);
        *(uint4*)&Vs[row * VA_STRIDE + c8] =
            *(const uint4*)((const unsigned short*)g_Vh + base + (size_t)row * Dv + c8);
    }
    __syncthreads();

    // z: column sums of K (fp32)
    if (t < 64) {
        float s = 0.f;
        for (int tt = 0; tt < 128; tt++) s += __half2float(Kt[t * KT_STRIDE + tt]);
        g_z[(size_t)(bh * NCv + c) * HDv + t] = s;
    }

    uint32_t ktb = smem_u32(Kt);
    uint32_t vsb = smem_u32(Vs);

    int wm = wid * 16;
    float cS[8][4];
#pragma unroll
    for (int nb = 0; nb < 8; nb++)
#pragma unroll
        for (int q = 0; q < 4; q++) cS[nb][q] = 0.f;

    int arow = lane & 15, acol8 = (lane >> 4) << 3;
#pragma unroll
    for (int ks = 0; ks < 8; ks++) {
        uint32_t a[4];
        ldsm_x4(a, ktb + (uint32_t)((wm + arow) * KT_STRIDE + ks * 16 + acol8) * 2);
#pragma unroll
        for (int p = 0; p < 4; p++) {
            uint32_t r[4];
            ldsm_x4_t(r, vsb + (uint32_t)((ks * 16 + arow) * VA_STRIDE + p * 16 + acol8) * 2);
            mma16816(cS[2 * p],     a, r[0], r[1]);
            mma16816(cS[2 * p + 1], a, r[2], r[3]);
        }
    }

    float* Sg = g_S + ((size_t)(bh * NCv + c)) * (HDv * HDv);
    int d0 = wm + (lane >> 2);
    int e0 = (lane & 3) * 2;
#pragma unroll
    for (int nb = 0; nb < 8; nb++) {
        Sg[d0 * 64 + nb * 8 + e0]           = cS[nb][0];
        Sg[d0 * 64 + nb * 8 + e0 + 1]       = cS[nb][1];
        Sg[(d0 + 8) * 64 + nb * 8 + e0]     = cS[nb][2];
        Sg[(d0 + 8) * 64 + nb * 8 + e0 + 1] = cS[nb][3];
    }
}

// ---------------------------------------------------------------------------
// Phase B: exclusive prefix over the 32 chunks (per (b,h)). 64 blocks.
// ---------------------------------------------------------------------------
__global__ __launch_bounds__(256)
void phaseB_kernel()
{
    int bh = blockIdx.x;
    int t  = threadIdx.x;

    float run[16];
#pragma unroll
    for (int r = 0; r < 16; r++) run[r] = 0.f;

    float* Sg = g_S + (size_t)bh * NCv * (HDv * HDv);
    for (int c = 0; c < NCv; c++) {
        float* p = Sg + (size_t)c * (HDv * HDv);
#pragma unroll
        for (int r = 0; r < 16; r++) {
            int idx = t + (r << 8);
            float v = p[idx];
            p[idx] = run[r];
            run[r] += v;
        }
    }
    if (t < 64) {
        float rz = 0.f;
        float* zg = g_z + (size_t)bh * NCv * HDv;
        for (int c = 0; c < NCv; c++) {
            float v = zg[c * HDv + t];
            zg[c * HDv + t] = rz;
            rz += v;
        }
    }
}

// ---------------------------------------------------------------------------
// Phase C (tensor): P = tril(QK^T); den = rowsum(P)+Q·z+eps;
// O = (P·V + Q·S_prev)/den, written fp16 into gA.
// 256 threads / 8 warps; warp w owns rows i0 = w*16.
// ---------------------------------------------------------------------------
#define QS_STRIDE 72
#define PHC_SMEM ((3 * 128 * QS_STRIDE + 64 * QS_STRIDE) * 2 + 64 * 4)

__global__ __launch_bounds__(256)
void phaseC_kernel()
{
    extern __shared__ __half smc[];
    __half* Qs = smc;
    __half* Ks = smc + 128 * QS_STRIDE;
    __half* Vs = smc + 2 * 128 * QS_STRIDE;
    __half* Sh = smc + 3 * 128 * QS_STRIDE;
    float*  zf = (float*)(smc + 3 * 128 * QS_STRIDE + 64 * QS_STRIDE);

    int blk = blockIdx.x;
    int c   = blk & (NCv - 1);
    int bh  = blk >> 5;
    int h   = bh & (Hv - 1);
    int b   = bh >> 4;
    int t   = threadIdx.x;
    int lane = t & 31, wid = t >> 5;

    size_t base = ((size_t)(b * Tv + c * Cv)) * Dv + h * HDv;

    for (int idx = t; idx < 128 * 8; idx += 256) {
        int row = idx >> 3, c8 = (idx & 7) << 3;
        size_t go = base + (size_t)row * Dv + c8;
        uint32_t so = (uint32_t)(row * QS_STRIDE + c8);
        *(uint4*)&Qs[so] = *(const uint4*)((const unsigned short*)g_Qh + go);
        *(uint4*)&Ks[so] = *(const uint4*)((const unsigned short*)g_Kh + go);
        *(uint4*)&Vs[so] = *(const uint4*)((const unsigned short*)g_Vh + go);
    }
    const float* Sg = g_S + ((size_t)(bh * NCv + c)) * (HDv * HDv);
    for (int idx = t; idx < 4096; idx += 256) {
        int d = idx >> 6, e = idx & 63;
        Sh[d * QS_STRIDE + e] = __float2half_rn(Sg[idx]);
    }
    if (t < 64) zf[t] = g_z[(size_t)(bh * NCv + c) * HDv + t];
    __syncthreads();

    uint32_t qsb = smem_u32(Qs), ksb = smem_u32(Ks), vsb = smem_u32(Vs), shb = smem_u32(Sh);

    int i0 = wid * 16;
    int arow = lane & 15, acol8 = (lane >> 4) << 3;

    // Q A-fragments (4 ksteps over d)
    uint32_t aQ[4][4];
#pragma unroll
    for (int ks = 0; ks < 4; ks++)
        ldsm_x4(aQ[ks], qsb + (uint32_t)((i0 + arow) * QS_STRIDE + ks * 16 + acol8) * 2);

    // P = Q K^T (fp32 frags, 16 n-blocks of 8)
    float cP[16][4];
#pragma unroll
    for (int nb = 0; nb < 16; nb++)
#pragma unroll
        for (int q = 0; q < 4; q++) cP[nb][q] = 0.f;

#pragma unroll
    for (int ks = 0; ks < 4; ks++) {
#pragma unroll
        for (int jb = 0; jb < 8; jb++) {   // j blocks of 16
            uint32_t r[4];
            ldsm_x4(r, ksb + (uint32_t)((jb * 16 + arow) * QS_STRIDE + ks * 16 + acol8) * 2);
            mma16816(cP[2 * jb],     aQ[ks], r[0], r[2]);   // rows j0-7
            mma16816(cP[2 * jb + 1], aQ[ks], r[1], r[3]);   // rows j8-15
        }
    }

    // Causal mask + rowsums
    int r0 = i0 + (lane >> 2);
    int cb = (lane & 3) * 2;
    float rs0 = 0.f, rs1 = 0.f;
#pragma unroll
    for (int nb = 0; nb < 16; nb++) {
        int j0 = nb * 8 + cb;
        if (j0     > r0)     cP[nb][0] = 0.f;
        if (j0 + 1 > r0)     cP[nb][1] = 0.f;
        if (j0     > r0 + 8) cP[nb][2] = 0.f;
        if (j0 + 1 > r0 + 8) cP[nb][3] = 0.f;
        rs0 += cP[nb][0] + cP[nb][1];
        rs1 += cP[nb][2] + cP[nb][3];
    }
    rs0 += __shfl_xor_sync(0xffffffffu, rs0, 1);
    rs0 += __shfl_xor_sync(0xffffffffu, rs0, 2);
    rs1 += __shfl_xor_sync(0xffffffffu, rs1, 1);
    rs1 += __shfl_xor_sync(0xffffffffu, rs1, 2);

    float qz0 = 0.f, qz1 = 0.f;
    for (int d = 0; d < 64; d++) {
        float zz = zf[d];
        qz0 += __half2float(Qs[r0 * QS_STRIDE + d]) * zz;
        qz1 += __half2float(Qs[(r0 + 8) * QS_STRIDE + d]) * zz;
    }
    float inv0 = 1.f / (rs0 + qz0 + 1e-6f);
    float inv1 = 1.f / (rs1 + qz1 + 1e-6f);

    // Pack P -> A fragments (8 j-ksteps)
    uint32_t aP[8][4];
#pragma unroll
    for (int jk = 0; jk < 8; jk++) {
        aP[jk][0] = pack_h2(cP[2 * jk][0],     cP[2 * jk][1]);
        aP[jk][1] = pack_h2(cP[2 * jk][2],     cP[2 * jk][3]);
        aP[jk][2] = pack_h2(cP[2 * jk + 1][0], cP[2 * jk + 1][1]);
        aP[jk][3] = pack_h2(cP[2 * jk + 1][2], cP[2 * jk + 1][3]);
    }

    // O = P V + Q S_prev
    float cO[8][4];
#pragma unroll
    for (int nb = 0; nb < 8; nb++)
#pragma unroll
        for (int q = 0; q < 4; q++) cO[nb][q] = 0.f;

#pragma unroll
    for (int jk = 0; jk < 8; jk++) {
#pragma unroll
        for (int p = 0; p < 4; p++) {
            uint32_t r[4];
            ldsm_x4_t(r, vsb + (uint32_t)((jk * 16 + arow) * QS_STRIDE + p * 16 + acol8) * 2);
            mma16816(cO[2 * p],     aP[jk], r[0], r[1]);
            mma16816(cO[2 * p + 1], aP[jk], r[2], r[3]);
        }
    }
#pragma unroll
    for (int ks = 0; ks < 4; ks++) {
#pragma unroll
        for (int p = 0; p < 4; p++) {
            uint32_t r[4];
            ldsm_x4_t(r, shb + (uint32_t)((ks * 16 + arow) * QS_STRIDE + p * 16 + acol8) * 2);
            mma16816(cO[2 * p],     aQ[ks], r[0], r[1]);
            mma16816(cO[2 * p + 1], aQ[ks], r[2], r[3]);
        }
    }

    // Scale by 1/den, store fp16 Y into gA
    unsigned short* Yg = (unsigned short*)gA + base;
#pragma unroll
    for (int nb = 0; nb < 8; nb++) {
        int e = nb * 8 + cb;
        *(uint32_t*)(Yg + (size_t)r0 * Dv + e)       = pack_h2(cO[nb][0] * inv0, cO[nb][1] * inv0);
        *(uint32_t*)(Yg + (size_t)(r0 + 8) * Dv + e) = pack_h2(cO[nb][2] * inv1, cO[nb][3] * inv1);
    }
}

// ---------------------------------------------------------------------------
// Launch
// ---------------------------------------------------------------------------
extern "C" void kernel_launch(void* const* d_in, const int* in_sizes, int n_in,
                              void* d_out, int out_size)
{
    const float* x  = (const float*)d_in[0];
    const float* Wq = (const float*)d_in[1];
    const float* Wk = (const float*)d_in[2];
    const float* Wv = (const float*)d_in[3];
    const float* Wo = (const float*)d_in[4];
    float* out = (float*)d_out;

    cudaFuncSetAttribute(mma_gemm_kernel,
                         cudaFuncAttributeMaxDynamicSharedMemorySize, GEMM_SMEM);
    cudaFuncSetAttribute(phaseC_kernel,
                         cudaFuncAttributeMaxDynamicSharedMemorySize, PHC_SMEM);

    convW_kernel<<<1024, 256>>>(Wq, 0);
    convW_kernel<<<1024, 256>>>(Wk, 1);
    convW_kernel<<<1024, 256>>>(Wv, 2);
    convW_kernel<<<1024, 256>>>(Wo, 3);

    convA_kernel<<<Mv * Dv / 1024, 256>>>(x);

    dim3 gqkv(1024 / 128, Mv / 128, 3);
    mma_gemm_kernel<<<gqkv, 128, GEMM_SMEM>>>(-1, nullptr, 0, 0);  // fp16 Q/K/V

    phaseA_kernel<<<Bv * Hv * NCv, 128>>>();
    phaseB_kernel<<<Bv * Hv, 256>>>();
    phaseC_kernel<<<Bv * Hv * NCv, 256, PHC_SMEM>>>();             // fp16 Y into gA

    dim3 go(1024 / 128, Mv / 128);
    mma_gemm_kernel<<<go, 128, GEMM_SMEM>>>(3, out, 3, 0);         // out = Y@Wo
}

// round 7
// speedup vs baseline: 5.4581x; 1.0174x over previous
#include <cuda_runtime.h>
#include <cuda_fp16.h>
#include <math.h>
#include <stdint.h>

// Problem constants
#define Bv   4
#define Tv   4096
#define Dv   1024
#define Hv   16
#define HDv  64
#define Cv   128
#define NCv  32            // Tv / Cv
#define Mv   (Bv*Tv)       // 16384

// ---------------------------------------------------------------------------
// Scratch (device globals; no allocation allowed)
// ---------------------------------------------------------------------------
__device__ __align__(16) float g_S[(size_t)Bv * Hv * NCv * HDv * HDv];
__device__ __align__(16) float g_z[(size_t)Bv * Hv * NCv * HDv];

__device__ __align__(16) __half gA[(size_t)Mv * Dv];   // x (QKV GEMMs), then Y (Wo GEMM)
__device__ __align__(16) __half gW[4 * 1024 * 1024];   // [wsel][K][N] fp16
__device__ __align__(16) __half g_Qh[(size_t)Mv * Dv]; // feature-mapped Q (fp16)
__device__ __align__(16) __half g_Kh[(size_t)Mv * Dv]; // feature-mapped K (fp16)
__device__ __align__(16) __half g_Vh[(size_t)Mv * Dv]; // V (fp16)

// ---------------------------------------------------------------------------
// PTX helpers
// ---------------------------------------------------------------------------
__device__ __forceinline__ uint32_t smem_u32(const void* p) {
    uint32_t a;
    asm("{ .reg .u64 t; cvta.to.shared.u64 t, %1; cvt.u32.u64 %0, t; }" : "=r"(a) : "l"(p));
    return a;
}

__device__ __forceinline__ void cp_async16(uint32_t saddr, const void* g) {
    asm volatile("cp.async.cg.shared.global [%0], [%1], 16;" :: "r"(saddr), "l"(g) : "memory");
}

__device__ __forceinline__ void ldsm_x4(uint32_t* r, uint32_t addr) {
    asm volatile("ldmatrix.sync.aligned.m8n8.x4.shared.b16 {%0,%1,%2,%3}, [%4];"
                 : "=r"(r[0]), "=r"(r[1]), "=r"(r[2]), "=r"(r[3]) : "r"(addr));
}
__device__ __forceinline__ void ldsm_x4_t(uint32_t* r, uint32_t addr) {
    asm volatile("ldmatrix.sync.aligned.m8n8.x4.trans.shared.b16 {%0,%1,%2,%3}, [%4];"
                 : "=r"(r[0]), "=r"(r[1]), "=r"(r[2]), "=r"(r[3]) : "r"(addr));
}

__device__ __forceinline__ void mma16816(float* c, const uint32_t* a, uint32_t b0, uint32_t b1) {
    asm volatile(
        "mma.sync.aligned.m16n8k16.row.col.f32.f16.f16.f32 "
        "{%0,%1,%2,%3}, {%4,%5,%6,%7}, {%8,%9}, {%0,%1,%2,%3};"
        : "+f"(c[0]), "+f"(c[1]), "+f"(c[2]), "+f"(c[3])
        : "r"(a[0]), "r"(a[1]), "r"(a[2]), "r"(a[3]), "r"(b0), "r"(b1));
}

__device__ __forceinline__ uint32_t pack_h2(float lo, float hi) {
    __half2 h = __floats2half2_rn(lo, hi);
    return *(uint32_t*)&h;
}

// ---------------------------------------------------------------------------
// fp32 -> fp16 conversions
// ---------------------------------------------------------------------------
__global__ __launch_bounds__(256)
void convA_kernel(const float* __restrict__ src)
{
    size_t i = ((size_t)blockIdx.x * 256 + threadIdx.x) * 4;
    float4 v = *(const float4*)(src + i);
    ushort4 h;
    h.x = __half_as_ushort(__float2half_rn(v.x));
    h.y = __half_as_ushort(__float2half_rn(v.y));
    h.z = __half_as_ushort(__float2half_rn(v.z));
    h.w = __half_as_ushort(__float2half_rn(v.w));
    *(ushort4*)((unsigned short*)gA + i) = h;
}

// Fused: blockIdx.y selects which weight matrix
__global__ __launch_bounds__(256)
void convW_kernel(const float* __restrict__ W0, const float* __restrict__ W1,
                  const float* __restrict__ W2, const float* __restrict__ W3)
{
    int wsel = blockIdx.y;
    const float* W = (wsel == 0) ? W0 : (wsel == 1) ? W1 : (wsel == 2) ? W2 : W3;
    size_t i = ((size_t)blockIdx.x * 256 + threadIdx.x) * 4;
    float4 v = *(const float4*)(W + i);
    ushort4 h;
    h.x = __half_as_ushort(__float2half_rn(v.x));
    h.y = __half_as_ushort(__float2half_rn(v.y));
    h.z = __half_as_ushort(__float2half_rn(v.z));
    h.w = __half_as_ushort(__float2half_rn(v.w));
    *(ushort4*)((unsigned short*)(gW + (size_t)wsel * 1024 * 1024) + i) = h;
}

// ---------------------------------------------------------------------------
// fp16 HMMA GEMM: C = A[M,K] @ W[K,N]. CTA 128x128, BK=32, 4-stage cp.async,
// 4 warps (64x64 warp tiles), target 3 CTAs/SM (HMMA-issue saturation).
// ---------------------------------------------------------------------------
#define ASTRIDE 40
#define BSTRIDE 136
#define A_SM    (128 * ASTRIDE * 2)      // 10240
#define B_SM    (32 * BSTRIDE * 2)       // 8704
#define STAGE_BYTES (A_SM + B_SM)        // 18944
#define GEMM_SMEM (4 * STAGE_BYTES)      // 75776

__device__ __forceinline__ void gemm_load_stage(
    uint32_t sb, int t, int m0, int n0, int kt,
    const __half* pA, const __half* pB)
{
    int k0 = kt * 32;
#pragma unroll
    for (int it = 0; it < 4; it++) {
        int idx = t + it * 128;
        int row = idx >> 2, c8 = (idx & 3) << 3;
        cp_async16(sb + (uint32_t)(row * ASTRIDE + c8) * 2,
                   pA + (size_t)(m0 + row) * 1024 + k0 + c8);
    }
#pragma unroll
    for (int it = 0; it < 4; it++) {
        int idx = t + it * 128;
        int row = idx >> 4, c8 = (idx & 15) << 3;
        cp_async16(sb + A_SM + (uint32_t)(row * BSTRIDE + c8) * 2,
                   pB + (size_t)(k0 + row) * 1024 + n0 + c8);
    }
    asm volatile("cp.async.commit_group;" ::: "memory");
}

__global__ __launch_bounds__(128, 3)
void mma_gemm_kernel(int wsel, float* __restrict__ Cext, int csel, int fmap)
{
    extern __shared__ __half smh[];
    if (wsel < 0) { wsel = blockIdx.z; csel = blockIdx.z; fmap = (blockIdx.z < 2); }

    const __half* pA = gA;
    const __half* pB = gW + (size_t)wsel * 1024 * 1024;

    int t = threadIdx.x, lane = t & 31, wid = t >> 5;
    int n0 = blockIdx.x * 128;
    int m0 = blockIdx.y * 128;
    uint32_t sbase = smem_u32(smh);

    int wm = (wid >> 1) * 64;
    int wn = (wid & 1) * 64;

    float acc[4][8][4];
#pragma unroll
    for (int mi = 0; mi < 4; mi++)
#pragma unroll
        for (int nt = 0; nt < 8; nt++)
#pragma unroll
            for (int q = 0; q < 4; q++) acc[mi][nt][q] = 0.f;

    gemm_load_stage(sbase, t, m0, n0, 0, pA, pB);
    gemm_load_stage(sbase + STAGE_BYTES, t, m0, n0, 1, pA, pB);
    gemm_load_stage(sbase + 2 * STAGE_BYTES, t, m0, n0, 2, pA, pB);

    for (int kt = 0; kt < 32; kt++) {
        if (kt <= 29)      asm volatile("cp.async.wait_group 2;" ::: "memory");
        else if (kt == 30) asm volatile("cp.async.wait_group 1;" ::: "memory");
        else               asm volatile("cp.async.wait_group 0;" ::: "memory");
        __syncthreads();
        if (kt + 3 < 32)
            gemm_load_stage(sbase + (uint32_t)((kt + 3) & 3) * STAGE_BYTES,
                            t, m0, n0, kt + 3, pA, pB);

        uint32_t sb = sbase + (uint32_t)(kt & 3) * STAGE_BYTES;
#pragma unroll
        for (int ks = 0; ks < 2; ks++) {
            uint32_t aF[4][4], bF[16];
            int arow = lane & 15;
            int acol = ks * 16 + ((lane >> 4) << 3);
#pragma unroll
            for (int mi = 0; mi < 4; mi++)
                ldsm_x4(aF[mi], sb + (uint32_t)((wm + mi * 16 + arow) * ASTRIDE + acol) * 2);

            int brow = ks * 16 + (lane & 15);
#pragma unroll
            for (int p = 0; p < 4; p++) {
                int bcol = wn + p * 16 + ((lane >> 4) << 3);
                ldsm_x4_t(&bF[p * 4], sb + A_SM + (uint32_t)(brow * BSTRIDE + bcol) * 2);
            }
#pragma unroll
            for (int mi = 0; mi < 4; mi++)
#pragma unroll
                for (int nt = 0; nt < 8; nt++)
                    mma16816(acc[mi][nt], aF[mi],
                             bF[(nt >> 1) * 4 + (nt & 1) * 2], bF[(nt >> 1) * 4 + (nt & 1) * 2 + 1]);
        }
    }

    int rbase = m0 + wm + (lane >> 2);
    int cb0 = wn + (lane & 3) * 2;
#pragma unroll
    for (int mi = 0; mi < 4; mi++) {
        int row = rbase + mi * 16;
#pragma unroll
        for (int nt = 0; nt < 8; nt++) {
            float v0 = acc[mi][nt][0], v1 = acc[mi][nt][1];
            float v2 = acc[mi][nt][2], v3 = acc[mi][nt][3];
            if (fmap) {
                v0 = v0 > 0.f ? v0 + 1.f : expf(v0);
                v1 = v1 > 0.f ? v1 + 1.f : expf(v1);
                v2 = v2 > 0.f ? v2 + 1.f : expf(v2);
                v3 = v3 > 0.f ? v3 + 1.f : expf(v3);
            }
            if (csel < 3) {
                __half* Ch = (csel == 0) ? g_Qh : (csel == 1) ? g_Kh : g_Vh;
                *(uint32_t*)((unsigned short*)Ch + (size_t)row * 1024 + n0 + cb0 + nt * 8)
                    = pack_h2(v0, v1);
                *(uint32_t*)((unsigned short*)Ch + (size_t)(row + 8) * 1024 + n0 + cb0 + nt * 8)
                    = pack_h2(v2, v3);
            } else {
                float2 o0; o0.x = v0; o0.y = v1;
                float2 o1; o1.x = v2; o1.y = v3;
                *(float2*)(Cext + (size_t)row * 1024 + n0 + cb0 + nt * 8) = o0;
                *(float2*)(Cext + (size_t)(row + 8) * 1024 + n0 + cb0 + nt * 8) = o1;
            }
        }
    }
}

// ---------------------------------------------------------------------------
// Phase A (tensor): S_c = K_c^T V_c (64x64 fp32), z_c = col sums of K.
// ---------------------------------------------------------------------------
#define KT_STRIDE 136
#define VA_STRIDE 72

__global__ __launch_bounds__(128)
void phaseA_kernel()
{
    __shared__ __half Kt[64 * KT_STRIDE];
    __shared__ __half Vs[128 * VA_STRIDE];

    int blk = blockIdx.x;
    int c   = blk & (NCv - 1);
    int bh  = blk >> 5;
    int h   = bh & (Hv - 1);
    int b   = bh >> 4;
    int t   = threadIdx.x;
    int lane = t & 31, wid = t >> 5;

    size_t base = ((size_t)(b * Tv + c * Cv)) * Dv + h * HDv;

    for (int idx = t; idx < 128 * 8; idx += 128) {
        int row = idx >> 3, c8 = (idx & 7) << 3;
        ushort4 kq = *(const ushort4*)((const unsigned short*)g_Kh + base + (size_t)row * Dv + c8);
        unsigned short kk[8];
        kk[0] = kq.x; kk[1] = kq.y; kk[2] = kq.z; kk[3] = kq.w;
        ushort4 kq2 = *(const ushort4*)((const unsigned short*)g_Kh + base + (size_t)row * Dv + c8 + 4);
        kk[4] = kq2.x; kk[5] = kq2.y; kk[6] = kq2.z; kk[7] = kq2.w;
#pragma unroll
        for (int q = 0; q < 8; q++)
            Kt[(c8 + q) * KT_STRIDE + row] = __ushort_as_half(kk[q]);
        *(uint4*)&Vs[row * VA_STRIDE + c8] =
            *(const uint4*)((const unsigned short*)g_Vh + base + (size_t)row * Dv + c8);
    }
    __syncthreads();

    if (t < 64) {
        float s = 0.f;
        for (int tt = 0; tt < 128; tt++) s += __half2float(Kt[t * KT_STRIDE + tt]);
        g_z[(size_t)(bh * NCv + c) * HDv + t] = s;
    }

    uint32_t ktb = smem_u32(Kt);
    uint32_t vsb = smem_u32(Vs);

    int wm = wid * 16;
    float cS[8][4];
#pragma unroll
    for (int nb = 0; nb < 8; nb++)
#pragma unroll
        for (int q = 0; q < 4; q++) cS[nb][q] = 0.f;

    int arow = lane & 15, acol8 = (lane >> 4) << 3;
#pragma unroll
    for (int ks = 0; ks < 8; ks++) {
        uint32_t a[4];
        ldsm_x4(a, ktb + (uint32_t)((wm + arow) * KT_STRIDE + ks * 16 + acol8) * 2);
#pragma unroll
        for (int p = 0; p < 4; p++) {
            uint32_t r[4];
            ldsm_x4_t(r, vsb + (uint32_t)((ks * 16 + arow) * VA_STRIDE + p * 16 + acol8) * 2);
            mma16816(cS[2 * p],     a, r[0], r[1]);
            mma16816(cS[2 * p + 1], a, r[2], r[3]);
        }
    }

    float* Sg = g_S + ((size_t)(bh * NCv + c)) * (HDv * HDv);
    int d0 = wm + (lane >> 2);
    int e0 = (lane & 3) * 2;
#pragma unroll
    for (int nb = 0; nb < 8; nb++) {
        Sg[d0 * 64 + nb * 8 + e0]           = cS[nb][0];
        Sg[d0 * 64 + nb * 8 + e0 + 1]       = cS[nb][1];
        Sg[(d0 + 8) * 64 + nb * 8 + e0]     = cS[nb][2];
        Sg[(d0 + 8) * 64 + nb * 8 + e0 + 1] = cS[nb][3];
    }
}

// ---------------------------------------------------------------------------
// Phase B: exclusive prefix over the 32 chunks (per (b,h)). 64 blocks.
// ---------------------------------------------------------------------------
__global__ __launch_bounds__(256)
void phaseB_kernel()
{
    int bh = blockIdx.x;
    int t  = threadIdx.x;

    float run[16];
#pragma unroll
    for (int r = 0; r < 16; r++) run[r] = 0.f;

    float* Sg = g_S + (size_t)bh * NCv * (HDv * HDv);
    for (int c = 0; c < NCv; c++) {
        float* p = Sg + (size_t)c * (HDv * HDv);
#pragma unroll
        for (int r = 0; r < 16; r++) {
            int idx = t + (r << 8);
            float v = p[idx];
            p[idx] = run[r];
            run[r] += v;
        }
    }
    if (t < 64) {
        float rz = 0.f;
        float* zg = g_z + (size_t)bh * NCv * HDv;
        for (int c = 0; c < NCv; c++) {
            float v = zg[c * HDv + t];
            zg[c * HDv + t] = rz;
            rz += v;
        }
    }
}

// ---------------------------------------------------------------------------
// Phase C (tensor): P = tril(QK^T); den = rowsum(P)+Q·z+eps;
// O = (P·V + Q·S_prev)/den, written fp16 into gA.
// ---------------------------------------------------------------------------
#define QS_STRIDE 72
#define PHC_SMEM ((3 * 128 * QS_STRIDE + 64 * QS_STRIDE) * 2 + 64 * 4)

__global__ __launch_bounds__(256)
void phaseC_kernel()
{
    extern __shared__ __half smc[];
    __half* Qs = smc;
    __half* Ks = smc + 128 * QS_STRIDE;
    __half* Vs = smc + 2 * 128 * QS_STRIDE;
    __half* Sh = smc + 3 * 128 * QS_STRIDE;
    float*  zf = (float*)(smc + 3 * 128 * QS_STRIDE + 64 * QS_STRIDE);

    int blk = blockIdx.x;
    int c   = blk & (NCv - 1);
    int bh  = blk >> 5;
    int h   = bh & (Hv - 1);
    int b   = bh >> 4;
    int t   = threadIdx.x;
    int lane = t & 31, wid = t >> 5;

    size_t base = ((size_t)(b * Tv + c * Cv)) * Dv + h * HDv;

    for (int idx = t; idx < 128 * 8; idx += 256) {
        int row = idx >> 3, c8 = (idx & 7) << 3;
        size_t go = base + (size_t)row * Dv + c8;
        uint32_t so = (uint32_t)(row * QS_STRIDE + c8);
        *(uint4*)&Qs[so] = *(const uint4*)((const unsigned short*)g_Qh + go);
        *(uint4*)&Ks[so] = *(const uint4*)((const unsigned short*)g_Kh + go);
        *(uint4*)&Vs[so] = *(const uint4*)((const unsigned short*)g_Vh + go);
    }
    const float* Sg = g_S + ((size_t)(bh * NCv + c)) * (HDv * HDv);
    for (int idx = t; idx < 4096; idx += 256) {
        int d = idx >> 6, e = idx & 63;
        Sh[d * QS_STRIDE + e] = __float2half_rn(Sg[idx]);
    }
    if (t < 64) zf[t] = g_z[(size_t)(bh * NCv + c) * HDv + t];
    __syncthreads();

    uint32_t qsb = smem_u32(Qs), ksb = smem_u32(Ks), vsb = smem_u32(Vs), shb = smem_u32(Sh);

    int i0 = wid * 16;
    int arow = lane & 15, acol8 = (lane >> 4) << 3;

    uint32_t aQ[4][4];
#pragma unroll
    for (int ks = 0; ks < 4; ks++)
        ldsm_x4(aQ[ks], qsb + (uint32_t)((i0 + arow) * QS_STRIDE + ks * 16 + acol8) * 2);

    float cP[16][4];
#pragma unroll
    for (int nb = 0; nb < 16; nb++)
#pragma unroll
        for (int q = 0; q < 4; q++) cP[nb][q] = 0.f;

#pragma unroll
    for (int ks = 0; ks < 4; ks++) {
#pragma unroll
        for (int jb = 0; jb < 8; jb++) {
            uint32_t r[4];
            ldsm_x4(r, ksb + (uint32_t)((jb * 16 + arow) * QS_STRIDE + ks * 16 + acol8) * 2);
            mma16816(cP[2 * jb],     aQ[ks], r[0], r[2]);
            mma16816(cP[2 * jb + 1], aQ[ks], r[1], r[3]);
        }
    }

    int r0 = i0 + (lane >> 2);
    int cb = (lane & 3) * 2;
    float rs0 = 0.f, rs1 = 0.f;
#pragma unroll
    for (int nb = 0; nb < 16; nb++) {
        int j0 = nb * 8 + cb;
        if (j0     > r0)     cP[nb][0] = 0.f;
        if (j0 + 1 > r0)     cP[nb][1] = 0.f;
        if (j0     > r0 + 8) cP[nb][2] = 0.f;
        if (j0 + 1 > r0 + 8) cP[nb][3] = 0.f;
        rs0 += cP[nb][0] + cP[nb][1];
        rs1 += cP[nb][2] + cP[nb][3];
    }
    rs0 += __shfl_xor_sync(0xffffffffu, rs0, 1);
    rs0 += __shfl_xor_sync(0xffffffffu, rs0, 2);
    rs1 += __shfl_xor_sync(0xffffffffu, rs1, 1);
    rs1 += __shfl_xor_sync(0xffffffffu, rs1, 2);

    float qz0 = 0.f, qz1 = 0.f;
    for (int d = 0; d < 64; d++) {
        float zz = zf[d];
        qz0 += __half2float(Qs[r0 * QS_STRIDE + d]) * zz;
        qz1 += __half2float(Qs[(r0 + 8) * QS_STRIDE + d]) * zz;
    }
    float inv0 = 1.f / (rs0 + qz0 + 1e-6f);
    float inv1 = 1.f / (rs1 + qz1 + 1e-6f);

    uint32_t aP[8][4];
#pragma unroll
    for (int jk = 0; jk < 8; jk++) {
        aP[jk][0] = pack_h2(cP[2 * jk][0],     cP[2 * jk][1]);
        aP[jk][1] = pack_h2(cP[2 * jk][2],     cP[2 * jk][3]);
        aP[jk][2] = pack_h2(cP[2 * jk + 1][0], cP[2 * jk + 1][1]);
        aP[jk][3] = pack_h2(cP[2 * jk + 1][2], cP[2 * jk + 1][3]);
    }

    float cO[8][4];
#pragma unroll
    for (int nb = 0; nb < 8; nb++)
#pragma unroll
        for (int q = 0; q < 4; q++) cO[nb][q] = 0.f;

#pragma unroll
    for (int jk = 0; jk < 8; jk++) {
#pragma unroll
        for (int p = 0; p < 4; p++) {
            uint32_t r[4];
            ldsm_x4_t(r, vsb + (uint32_t)((jk * 16 + arow) * QS_STRIDE + p * 16 + acol8) * 2);
            mma16816(cO[2 * p],     aP[jk], r[0], r[1]);
            mma16816(cO[2 * p + 1], aP[jk], r[2], r[3]);
        }
    }
#pragma unroll
    for (int ks = 0; ks < 4; ks++) {
#pragma unroll
        for (int p = 0; p < 4; p++) {
            uint32_t r[4];
            ldsm_x4_t(r, shb + (uint32_t)((ks * 16 + arow) * QS_STRIDE + p * 16 + acol8) * 2);
            mma16816(cO[2 * p],     aQ[ks], r[0], r[1]);
            mma16816(cO[2 * p + 1], aQ[ks], r[2], r[3]);
        }
    }

    unsigned short* Yg = (unsigned short*)gA + base;
#pragma unroll
    for (int nb = 0; nb < 8; nb++) {
        int e = nb * 8 + cb;
        *(uint32_t*)(Yg + (size_t)r0 * Dv + e)       = pack_h2(cO[nb][0] * inv0, cO[nb][1] * inv0);
        *(uint32_t*)(Yg + (size_t)(r0 + 8) * Dv + e) = pack_h2(cO[nb][2] * inv1, cO[nb][3] * inv1);
    }
}

// ---------------------------------------------------------------------------
// Launch
// ---------------------------------------------------------------------------
extern "C" void kernel_launch(void* const* d_in, const int* in_sizes, int n_in,
                              void* d_out, int out_size)
{
    const float* x  = (const float*)d_in[0];
    const float* Wq = (const float*)d_in[1];
    const float* Wk = (const float*)d_in[2];
    const float* Wv = (const float*)d_in[3];
    const float* Wo = (const float*)d_in[4];
    float* out = (float*)d_out;

    cudaFuncSetAttribute(mma_gemm_kernel,
                         cudaFuncAttributeMaxDynamicSharedMemorySize, GEMM_SMEM);
    cudaFuncSetAttribute(phaseC_kernel,
                         cudaFuncAttributeMaxDynamicSharedMemorySize, PHC_SMEM);

    dim3 gw(1024, 4);
    convW_kernel<<<gw, 256>>>(Wq, Wk, Wv, Wo);
    convA_kernel<<<Mv * Dv / 1024, 256>>>(x);

    dim3 gqkv(1024 / 128, Mv / 128, 3);
    mma_gemm_kernel<<<gqkv, 128, GEMM_SMEM>>>(-1, nullptr, 0, 0);  // fp16 Q/K/V

    phaseA_kernel<<<Bv * Hv * NCv, 128>>>();
    phaseB_kernel<<<Bv * Hv, 256>>>();
    phaseC_kernel<<<Bv * Hv * NCv, 256, PHC_SMEM>>>();             // fp16 Y into gA

    dim3 go(1024 / 128, Mv / 128);
    mma_gemm_kernel<<<go, 128, GEMM_SMEM>>>(3, out, 3, 0);         // out = Y@Wo
}

// round 8
// speedup vs baseline: 5.5164x; 1.0107x over previous
#include <cuda_runtime.h>
#include <cuda_fp16.h>
#include <math.h>
#include <stdint.h>

// Problem constants
#define Bv   4
#define Tv   4096
#define Dv   1024
#define Hv   16
#define HDv  64
#define Cv   128
#define NCv  32            // Tv / Cv
#define Mv   (Bv*Tv)       // 16384

// ---------------------------------------------------------------------------
// Scratch (device globals; no allocation allowed)
// ---------------------------------------------------------------------------
__device__ __align__(16) float g_S[(size_t)Bv * Hv * NCv * HDv * HDv];
__device__ __align__(16) float g_z[(size_t)Bv * Hv * NCv * HDv];

__device__ __align__(16) __half gA[(size_t)Mv * Dv];   // x (QKV GEMMs), then Y (Wo GEMM)
__device__ __align__(16) __half gW[4 * 1024 * 1024];   // [wsel][K][N] fp16
__device__ __align__(16) __half g_Qh[(size_t)Mv * Dv];
__device__ __align__(16) __half g_Kh[(size_t)Mv * Dv];
__device__ __align__(16) __half g_Vh[(size_t)Mv * Dv];

// ---------------------------------------------------------------------------
// PTX helpers
// ---------------------------------------------------------------------------
__device__ __forceinline__ uint32_t smem_u32(const void* p) {
    uint32_t a;
    asm("{ .reg .u64 t; cvta.to.shared.u64 t, %1; cvt.u32.u64 %0, t; }" : "=r"(a) : "l"(p));
    return a;
}

__device__ __forceinline__ void cp_async16(uint32_t saddr, const void* g) {
    asm volatile("cp.async.cg.shared.global [%0], [%1], 16;" :: "r"(saddr), "l"(g) : "memory");
}

__device__ __forceinline__ void ldsm_x4(uint32_t* r, uint32_t addr) {
    asm volatile("ldmatrix.sync.aligned.m8n8.x4.shared.b16 {%0,%1,%2,%3}, [%4];"
                 : "=r"(r[0]), "=r"(r[1]), "=r"(r[2]), "=r"(r[3]) : "r"(addr));
}
__device__ __forceinline__ void ldsm_x4_t(uint32_t* r, uint32_t addr) {
    asm volatile("ldmatrix.sync.aligned.m8n8.x4.trans.shared.b16 {%0,%1,%2,%3}, [%4];"
                 : "=r"(r[0]), "=r"(r[1]), "=r"(r[2]), "=r"(r[3]) : "r"(addr));
}

__device__ __forceinline__ void mma16816(float* c, const uint32_t* a, uint32_t b0, uint32_t b1) {
    asm volatile(
        "mma.sync.aligned.m16n8k16.row.col.f32.f16.f16.f32 "
        "{%0,%1,%2,%3}, {%4,%5,%6,%7}, {%8,%9}, {%0,%1,%2,%3};"
        : "+f"(c[0]), "+f"(c[1]), "+f"(c[2]), "+f"(c[3])
        : "r"(a[0]), "r"(a[1]), "r"(a[2]), "r"(a[3]), "r"(b0), "r"(b1));
}

__device__ __forceinline__ uint32_t pack_h2(float lo, float hi) {
    __half2 h = __floats2half2_rn(lo, hi);
    return *(uint32_t*)&h;
}

// ---------------------------------------------------------------------------
// Fused fp32 -> fp16 conversion: blocks [0, 16384) convert x into gA,
// blocks [16384, 16384+4096) convert the four weight matrices into gW.
// ---------------------------------------------------------------------------
#define CONV_A_BLOCKS (Mv * Dv / 1024)            // 16384
#define CONV_W_BLOCKS (4 * 1024 * 1024 / 1024)    // 4096

__global__ __launch_bounds__(256)
void conv_kernel(const float* __restrict__ x,
                 const float* __restrict__ W0, const float* __restrict__ W1,
                 const float* __restrict__ W2, const float* __restrict__ W3)
{
    int blk = blockIdx.x;
    const float* src;
    unsigned short* dst;
    size_t i;
    if (blk < CONV_A_BLOCKS) {
        src = x;
        dst = (unsigned short*)gA;
        i = ((size_t)blk * 256 + threadIdx.x) * 4;
    } else {
        int wblk = blk - CONV_A_BLOCKS;
        int wsel = wblk >> 10;                 // 1024 blocks per matrix
        src = (wsel == 0) ? W0 : (wsel == 1) ? W1 : (wsel == 2) ? W2 : W3;
        dst = (unsigned short*)(gW + (size_t)wsel * 1024 * 1024);
        i = ((size_t)(wblk & 1023) * 256 + threadIdx.x) * 4;
    }
    float4 v = *(const float4*)(src + i);
    ushort4 h;
    h.x = __half_as_ushort(__float2half_rn(v.x));
    h.y = __half_as_ushort(__float2half_rn(v.y));
    h.z = __half_as_ushort(__float2half_rn(v.z));
    h.w = __half_as_ushort(__float2half_rn(v.w));
    *(ushort4*)(dst + i) = h;
}

// ---------------------------------------------------------------------------
// fp16 HMMA GEMM: C = A[M,K] @ W[K,N]. CTA 128x128, BK=32, 4-stage cp.async,
// 4 warps (64x64 warp tiles), 3 CTAs/SM.
// ---------------------------------------------------------------------------
#define ASTRIDE 40
#define BSTRIDE 136
#define A_SM    (128 * ASTRIDE * 2)      // 10240
#define B_SM    (32 * BSTRIDE * 2)       // 8704
#define STAGE_BYTES (A_SM + B_SM)        // 18944
#define GEMM_SMEM (4 * STAGE_BYTES)      // 75776

__device__ __forceinline__ void gemm_load_stage(
    uint32_t sb, int t, int m0, int n0, int kt,
    const __half* pA, const __half* pB)
{
    int k0 = kt * 32;
#pragma unroll
    for (int it = 0; it < 4; it++) {
        int idx = t + it * 128;
        int row = idx >> 2, c8 = (idx & 3) << 3;
        cp_async16(sb + (uint32_t)(row * ASTRIDE + c8) * 2,
                   pA + (size_t)(m0 + row) * 1024 + k0 + c8);
    }
#pragma unroll
    for (int it = 0; it < 4; it++) {
        int idx = t + it * 128;
        int row = idx >> 4, c8 = (idx & 15) << 3;
        cp_async16(sb + A_SM + (uint32_t)(row * BSTRIDE + c8) * 2,
                   pB + (size_t)(k0 + row) * 1024 + n0 + c8);
    }
    asm volatile("cp.async.commit_group;" ::: "memory");
}

__global__ __launch_bounds__(128, 3)
void mma_gemm_kernel(int wsel, float* __restrict__ Cext, int csel, int fmap)
{
    extern __shared__ __half smh[];
    if (wsel < 0) { wsel = blockIdx.z; csel = blockIdx.z; fmap = (blockIdx.z < 2); }

    const __half* pA = gA;
    const __half* pB = gW + (size_t)wsel * 1024 * 1024;

    int t = threadIdx.x, lane = t & 31, wid = t >> 5;
    int n0 = blockIdx.x * 128;
    int m0 = blockIdx.y * 128;
    uint32_t sbase = smem_u32(smh);

    int wm = (wid >> 1) * 64;
    int wn = (wid & 1) * 64;

    float acc[4][8][4];
#pragma unroll
    for (int mi = 0; mi < 4; mi++)
#pragma unroll
        for (int nt = 0; nt < 8; nt++)
#pragma unroll
            for (int q = 0; q < 4; q++) acc[mi][nt][q] = 0.f;

    gemm_load_stage(sbase, t, m0, n0, 0, pA, pB);
    gemm_load_stage(sbase + STAGE_BYTES, t, m0, n0, 1, pA, pB);
    gemm_load_stage(sbase + 2 * STAGE_BYTES, t, m0, n0, 2, pA, pB);

    for (int kt = 0; kt < 32; kt++) {
        if (kt <= 29)      asm volatile("cp.async.wait_group 2;" ::: "memory");
        else if (kt == 30) asm volatile("cp.async.wait_group 1;" ::: "memory");
        else               asm volatile("cp.async.wait_group 0;" ::: "memory");
        __syncthreads();
        if (kt + 3 < 32)
            gemm_load_stage(sbase + (uint32_t)((kt + 3) & 3) * STAGE_BYTES,
                            t, m0, n0, kt + 3, pA, pB);

        uint32_t sb = sbase + (uint32_t)(kt & 3) * STAGE_BYTES;
#pragma unroll
        for (int ks = 0; ks < 2; ks++) {
            uint32_t aF[4][4], bF[16];
            int arow = lane & 15;
            int acol = ks * 16 + ((lane >> 4) << 3);
#pragma unroll
            for (int mi = 0; mi < 4; mi++)
                ldsm_x4(aF[mi], sb + (uint32_t)((wm + mi * 16 + arow) * ASTRIDE + acol) * 2);

            int brow = ks * 16 + (lane & 15);
#pragma unroll
            for (int p = 0; p < 4; p++) {
                int bcol = wn + p * 16 + ((lane >> 4) << 3);
                ldsm_x4_t(&bF[p * 4], sb + A_SM + (uint32_t)(brow * BSTRIDE + bcol) * 2);
            }
#pragma unroll
            for (int mi = 0; mi < 4; mi++)
#pragma unroll
                for (int nt = 0; nt < 8; nt++)
                    mma16816(acc[mi][nt], aF[mi],
                             bF[(nt >> 1) * 4 + (nt & 1) * 2], bF[(nt >> 1) * 4 + (nt & 1) * 2 + 1]);
        }
    }

    int rbase = m0 + wm + (lane >> 2);
    int cb0 = wn + (lane & 3) * 2;
#pragma unroll
    for (int mi = 0; mi < 4; mi++) {
        int row = rbase + mi * 16;
#pragma unroll
        for (int nt = 0; nt < 8; nt++) {
            float v0 = acc[mi][nt][0], v1 = acc[mi][nt][1];
            float v2 = acc[mi][nt][2], v3 = acc[mi][nt][3];
            if (fmap) {
                v0 = v0 > 0.f ? v0 + 1.f : expf(v0);
                v1 = v1 > 0.f ? v1 + 1.f : expf(v1);
                v2 = v2 > 0.f ? v2 + 1.f : expf(v2);
                v3 = v3 > 0.f ? v3 + 1.f : expf(v3);
            }
            if (csel < 3) {
                __half* Ch = (csel == 0) ? g_Qh : (csel == 1) ? g_Kh : g_Vh;
                *(uint32_t*)((unsigned short*)Ch + (size_t)row * 1024 + n0 + cb0 + nt * 8)
                    = pack_h2(v0, v1);
                *(uint32_t*)((unsigned short*)Ch + (size_t)(row + 8) * 1024 + n0 + cb0 + nt * 8)
                    = pack_h2(v2, v3);
            } else {
                float2 o0; o0.x = v0; o0.y = v1;
                float2 o1; o1.x = v2; o1.y = v3;
                *(float2*)(Cext + (size_t)row * 1024 + n0 + cb0 + nt * 8) = o0;
                *(float2*)(Cext + (size_t)(row + 8) * 1024 + n0 + cb0 + nt * 8) = o1;
            }
        }
    }
}

// ---------------------------------------------------------------------------
// Phase A (tensor): S_c = K_c^T V_c (64x64 fp32), z_c = col sums of K.
// K^T A-fragments built directly with ldmatrix.trans (no smem transpose).
// ---------------------------------------------------------------------------
#define PA_STRIDE 72

__global__ __launch_bounds__(128)
void phaseA_kernel()
{
    __shared__ __half Ks[128 * PA_STRIDE];
    __shared__ __half Vs[128 * PA_STRIDE];

    int blk = blockIdx.x;
    int c   = blk & (NCv - 1);
    int bh  = blk >> 5;
    int h   = bh & (Hv - 1);
    int b   = bh >> 4;
    int t   = threadIdx.x;
    int lane = t & 31, wid = t >> 5;

    size_t base = ((size_t)(b * Tv + c * Cv)) * Dv + h * HDv;

    for (int idx = t; idx < 128 * 8; idx += 128) {
        int row = idx >> 3, c8 = (idx & 7) << 3;
        size_t go = base + (size_t)row * Dv + c8;
        *(uint4*)&Ks[row * PA_STRIDE + c8] = *(const uint4*)((const unsigned short*)g_Kh + go);
        *(uint4*)&Vs[row * PA_STRIDE + c8] = *(const uint4*)((const unsigned short*)g_Vh + go);
    }
    __syncthreads();

    if (t < 64) {
        float s = 0.f;
        for (int tt = 0; tt < 128; tt++) s += __half2float(Ks[tt * PA_STRIDE + t]);
        g_z[(size_t)(bh * NCv + c) * HDv + t] = s;
    }

    uint32_t ksb = smem_u32(Ks);
    uint32_t vsb = smem_u32(Vs);

    int wm = wid * 16;
    float cS[8][4];
#pragma unroll
    for (int nb = 0; nb < 8; nb++)
#pragma unroll
        for (int q = 0; q < 4; q++) cS[nb][q] = 0.f;

    // A-frag (K^T) trans-ldsm lane mapping:
    //   mat g = lane>>3;  row = ks*16 + ((g>>1)<<3) + (lane&7);  col = wm + ((g&1)<<3)
    int a_rofs = ((lane >> 4) << 3) + (lane & 7);   // (g>>1)*8 + r
    int a_cofs = wm + (((lane >> 3) & 1) << 3);
    int brow = lane & 15, bcol8 = (lane >> 4) << 3;

#pragma unroll
    for (int ks = 0; ks < 8; ks++) {
        uint32_t a[4];
        ldsm_x4_t(a, ksb + (uint32_t)((ks * 16 + a_rofs) * PA_STRIDE + a_cofs) * 2);
#pragma unroll
        for (int p = 0; p < 4; p++) {
            uint32_t r[4];
            ldsm_x4_t(r, vsb + (uint32_t)((ks * 16 + brow) * PA_STRIDE + p * 16 + bcol8) * 2);
            mma16816(cS[2 * p],     a, r[0], r[1]);
            mma16816(cS[2 * p + 1], a, r[2], r[3]);
        }
    }

    float* Sg = g_S + ((size_t)(bh * NCv + c)) * (HDv * HDv);
    int d0 = wm + (lane >> 2);
    int e0 = (lane & 3) * 2;
#pragma unroll
    for (int nb = 0; nb < 8; nb++) {
        Sg[d0 * 64 + nb * 8 + e0]           = cS[nb][0];
        Sg[d0 * 64 + nb * 8 + e0 + 1]       = cS[nb][1];
        Sg[(d0 + 8) * 64 + nb * 8 + e0]     = cS[nb][2];
        Sg[(d0 + 8) * 64 + nb * 8 + e0 + 1] = cS[nb][3];
    }
}

// ---------------------------------------------------------------------------
// Phase B: exclusive prefix over the 32 chunks (per (b,h)). 64 blocks.
// ---------------------------------------------------------------------------
__global__ __launch_bounds__(256)
void phaseB_kernel()
{
    int bh = blockIdx.x;
    int t  = threadIdx.x;

    float run[16];
#pragma unroll
    for (int r = 0; r < 16; r++) run[r] = 0.f;

    float* Sg = g_S + (size_t)bh * NCv * (HDv * HDv);
    for (int c = 0; c < NCv; c++) {
        float* p = Sg + (size_t)c * (HDv * HDv);
#pragma unroll
        for (int r = 0; r < 16; r++) {
            int idx = t + (r << 8);
            float v = p[idx];
            p[idx] = run[r];
            run[r] += v;
        }
    }
    if (t < 64) {
        float rz = 0.f;
        float* zg = g_z + (size_t)bh * NCv * HDv;
        for (int c = 0; c < NCv; c++) {
            float v = zg[c * HDv + t];
            zg[c * HDv + t] = rz;
            rz += v;
        }
    }
}

// ---------------------------------------------------------------------------
// Phase C (tensor): P = tril(QK^T); den = rowsum(P)+Q·z+eps;
// O = (P·V + Q·S_prev)/den, written fp16 into gA.
// ---------------------------------------------------------------------------
#define QS_STRIDE 72
#define PHC_SMEM ((3 * 128 * QS_STRIDE + 64 * QS_STRIDE) * 2 + 64 * 4)

__global__ __launch_bounds__(256)
void phaseC_kernel()
{
    extern __shared__ __half smc[];
    __half* Qs = smc;
    __half* Ks = smc + 128 * QS_STRIDE;
    __half* Vs = smc + 2 * 128 * QS_STRIDE;
    __half* Sh = smc + 3 * 128 * QS_STRIDE;
    float*  zf = (float*)(smc + 3 * 128 * QS_STRIDE + 64 * QS_STRIDE);

    int blk = blockIdx.x;
    int c   = blk & (NCv - 1);
    int bh  = blk >> 5;
    int h   = bh & (Hv - 1);
    int b   = bh >> 4;
    int t   = threadIdx.x;
    int lane = t & 31, wid = t >> 5;

    size_t base = ((size_t)(b * Tv + c * Cv)) * Dv + h * HDv;

    for (int idx = t; idx < 128 * 8; idx += 256) {
        int row = idx >> 3, c8 = (idx & 7) << 3;
        size_t go = base + (size_t)row * Dv + c8;
        uint32_t so = (uint32_t)(row * QS_STRIDE + c8);
        *(uint4*)&Qs[so] = *(const uint4*)((const unsigned short*)g_Qh + go);
        *(uint4*)&Ks[so] = *(const uint4*)((const unsigned short*)g_Kh + go);
        *(uint4*)&Vs[so] = *(const uint4*)((const unsigned short*)g_Vh + go);
    }
    const float* Sg = g_S + ((size_t)(bh * NCv + c)) * (HDv * HDv);
    for (int idx = t; idx < 4096; idx += 256) {
        int d = idx >> 6, e = idx & 63;
        Sh[d * QS_STRIDE + e] = __float2half_rn(Sg[idx]);
    }
    if (t < 64) zf[t] = g_z[(size_t)(bh * NCv + c) * HDv + t];
    __syncthreads();

    uint32_t qsb = smem_u32(Qs), ksb = smem_u32(Ks), vsb = smem_u32(Vs), shb = smem_u32(Sh);

    int i0 = wid * 16;
    int arow = lane & 15, acol8 = (lane >> 4) << 3;

    uint32_t aQ[4][4];
#pragma unroll
    for (int ks = 0; ks < 4; ks++)
        ldsm_x4(aQ[ks], qsb + (uint32_t)((i0 + arow) * QS_STRIDE + ks * 16 + acol8) * 2);

    float cP[16][4];
#pragma unroll
    for (int nb = 0; nb < 16; nb++)
#pragma unroll
        for (int q = 0; q < 4; q++) cP[nb][q] = 0.f;

#pragma unroll
    for (int ks = 0; ks < 4; ks++) {
#pragma unroll
        for (int jb = 0; jb < 8; jb++) {
            uint32_t r[4];
            ldsm_x4(r, ksb + (uint32_t)((jb * 16 + arow) * QS_STRIDE + ks * 16 + acol8) * 2);
            mma16816(cP[2 * jb],     aQ[ks], r[0], r[2]);
            mma16816(cP[2 * jb + 1], aQ[ks], r[1], r[3]);
        }
    }

    int r0 = i0 + (lane >> 2);
    int cb = (lane & 3) * 2;
    float rs0 = 0.f, rs1 = 0.f;
#pragma unroll
    for (int nb = 0; nb < 16; nb++) {
        int j0 = nb * 8 + cb;
        if (j0     > r0)     cP[nb][0] = 0.f;
        if (j0 + 1 > r0)     cP[nb][1] = 0.f;
        if (j0     > r0 + 8) cP[nb][2] = 0.f;
        if (j0 + 1 > r0 + 8) cP[nb][3] = 0.f;
        rs0 += cP[nb][0] + cP[nb][1];
        rs1 += cP[nb][2] + cP[nb][3];
    }
    rs0 += __shfl_xor_sync(0xffffffffu, rs0, 1);
    rs0 += __shfl_xor_sync(0xffffffffu, rs0, 2);
    rs1 += __shfl_xor_sync(0xffffffffu, rs1, 1);
    rs1 += __shfl_xor_sync(0xffffffffu, rs1, 2);

    float qz0 = 0.f, qz1 = 0.f;
    for (int d = 0; d < 64; d++) {
        float zz = zf[d];
        qz0 += __half2float(Qs[r0 * QS_STRIDE + d]) * zz;
        qz1 += __half2float(Qs[(r0 + 8) * QS_STRIDE + d]) * zz;
    }
    float inv0 = 1.f / (rs0 + qz0 + 1e-6f);
    float inv1 = 1.f / (rs1 + qz1 + 1e-6f);

    uint32_t aP[8][4];
#pragma unroll
    for (int jk = 0; jk < 8; jk++) {
        aP[jk][0] = pack_h2(cP[2 * jk][0],     cP[2 * jk][1]);
        aP[jk][1] = pack_h2(cP[2 * jk][2],     cP[2 * jk][3]);
        aP[jk][2] = pack_h2(cP[2 * jk + 1][0], cP[2 * jk + 1][1]);
        aP[jk][3] = pack_h2(cP[2 * jk + 1][2], cP[2 * jk + 1][3]);
    }

    float cO[8][4];
#pragma unroll
    for (int nb = 0; nb < 8; nb++)
#pragma unroll
        for (int q = 0; q < 4; q++) cO[nb][q] = 0.f;

#pragma unroll
    for (int jk = 0; jk < 8; jk++) {
#pragma unroll
        for (int p = 0; p < 4; p++) {
            uint32_t r[4];
            ldsm_x4_t(r, vsb + (uint32_t)((jk * 16 + arow) * QS_STRIDE + p * 16 + acol8) * 2);
            mma16816(cO[2 * p],     aP[jk], r[0], r[1]);
            mma16816(cO[2 * p + 1], aP[jk], r[2], r[3]);
        }
    }
#pragma unroll
    for (int ks = 0; ks < 4; ks++) {
#pragma unroll
        for (int p = 0; p < 4; p++) {
            uint32_t r[4];
            ldsm_x4_t(r, shb + (uint32_t)((ks * 16 + arow) * QS_STRIDE + p * 16 + acol8) * 2);
            mma16816(cO[2 * p],     aQ[ks], r[0], r[1]);
            mma16816(cO[2 * p + 1], aQ[ks], r[2], r[3]);
        }
    }

    unsigned short* Yg = (unsigned short*)gA + base;
#pragma unroll
    for (int nb = 0; nb < 8; nb++) {
        int e = nb * 8 + cb;
        *(uint32_t*)(Yg + (size_t)r0 * Dv + e)       = pack_h2(cO[nb][0] * inv0, cO[nb][1] * inv0);
        *(uint32_t*)(Yg + (size_t)(r0 + 8) * Dv + e) = pack_h2(cO[nb][2] * inv1, cO[nb][3] * inv1);
    }
}

// ---------------------------------------------------------------------------
// Launch
// ---------------------------------------------------------------------------
extern "C" void kernel_launch(void* const* d_in, const int* in_sizes, int n_in,
                              void* d_out, int out_size)
{
    const float* x  = (const float*)d_in[0];
    const float* Wq = (const float*)d_in[1];
    const float* Wk = (const float*)d_in[2];
    const float* Wv = (const float*)d_in[3];
    const float* Wo = (const float*)d_in[4];
    float* out = (float*)d_out;

    cudaFuncSetAttribute(mma_gemm_kernel,
                         cudaFuncAttributeMaxDynamicSharedMemorySize, GEMM_SMEM);
    cudaFuncSetAttribute(phaseC_kernel,
                         cudaFuncAttributeMaxDynamicSharedMemorySize, PHC_SMEM);

    conv_kernel<<<CONV_A_BLOCKS + CONV_W_BLOCKS, 256>>>(x, Wq, Wk, Wv, Wo);

    dim3 gqkv(1024 / 128, Mv / 128, 3);
    mma_gemm_kernel<<<gqkv, 128, GEMM_SMEM>>>(-1, nullptr, 0, 0);  // fp16 Q/K/V

    phaseA_kernel<<<Bv * Hv * NCv, 128>>>();
    phaseB_kernel<<<Bv * Hv, 256>>>();
    phaseC_kernel<<<Bv * Hv * NCv, 256, PHC_SMEM>>>();             // fp16 Y into gA

    dim3 go(1024 / 128, Mv / 128);
    mma_gemm_kernel<<<go, 128, GEMM_SMEM>>>(3, out, 3, 0);         // out = Y@Wo
}

// round 9
// speedup vs baseline: 6.2679x; 1.1362x over previous
#include <cuda_runtime.h>
#include <cuda_fp16.h>
#include <math.h>
#include <stdint.h>

// Problem constants
#define Bv   4
#define Tv   4096
#define Dv   1024
#define Hv   16
#define HDv  64
#define Cv   128
#define NCv  32            // Tv / Cv
#define Mv   (Bv*Tv)       // 16384

// ---------------------------------------------------------------------------
// Scratch (device globals; no allocation allowed)
// ---------------------------------------------------------------------------
__device__ __align__(16) float g_S[(size_t)Bv * Hv * NCv * HDv * HDv];
__device__ __align__(16) float g_z[(size_t)Bv * Hv * NCv * HDv];

__device__ __align__(16) __half gA[(size_t)Mv * Dv];   // x (QKV GEMMs), then Y (Wo GEMM)
__device__ __align__(16) __half gW[4 * 1024 * 1024];   // [wsel][K][N] fp16
__device__ __align__(16) __half g_Qh[(size_t)Mv * Dv];
__device__ __align__(16) __half g_Kh[(size_t)Mv * Dv];
__device__ __align__(16) __half g_Vh[(size_t)Mv * Dv];

// ---------------------------------------------------------------------------
// PTX helpers
// ---------------------------------------------------------------------------
__device__ __forceinline__ uint32_t smem_u32(const void* p) {
    uint32_t a;
    asm("{ .reg .u64 t; cvta.to.shared.u64 t, %1; cvt.u32.u64 %0, t; }" : "=r"(a) : "l"(p));
    return a;
}

__device__ __forceinline__ void cp_async16(uint32_t saddr, const void* g) {
    asm volatile("cp.async.cg.shared.global [%0], [%1], 16;" :: "r"(saddr), "l"(g) : "memory");
}

__device__ __forceinline__ void ldsm_x4(uint32_t* r, uint32_t addr) {
    asm volatile("ldmatrix.sync.aligned.m8n8.x4.shared.b16 {%0,%1,%2,%3}, [%4];"
                 : "=r"(r[0]), "=r"(r[1]), "=r"(r[2]), "=r"(r[3]) : "r"(addr));
}
__device__ __forceinline__ void ldsm_x4_t(uint32_t* r, uint32_t addr) {
    asm volatile("ldmatrix.sync.aligned.m8n8.x4.trans.shared.b16 {%0,%1,%2,%3}, [%4];"
                 : "=r"(r[0]), "=r"(r[1]), "=r"(r[2]), "=r"(r[3]) : "r"(addr));
}

__device__ __forceinline__ void mma16816(float* c, const uint32_t* a, uint32_t b0, uint32_t b1) {
    asm volatile(
        "mma.sync.aligned.m16n8k16.row.col.f32.f16.f16.f32 "
        "{%0,%1,%2,%3}, {%4,%5,%6,%7}, {%8,%9}, {%0,%1,%2,%3};"
        : "+f"(c[0]), "+f"(c[1]), "+f"(c[2]), "+f"(c[3])
        : "r"(a[0]), "r"(a[1]), "r"(a[2]), "r"(a[3]), "r"(b0), "r"(b1));
}

__device__ __forceinline__ uint32_t pack_h2(float lo, float hi) {
    __half2 h = __floats2half2_rn(lo, hi);
    return *(uint32_t*)&h;
}

// ---------------------------------------------------------------------------
// Fused fp32 -> fp16 conversion: blocks [0, 16384) convert x into gA,
// blocks [16384, 16384+4096) convert the four weight matrices into gW.
// ---------------------------------------------------------------------------
#define CONV_A_BLOCKS (Mv * Dv / 1024)            // 16384
#define CONV_W_BLOCKS (4 * 1024 * 1024 / 1024)    // 4096

__global__ __launch_bounds__(256)
void conv_kernel(const float* __restrict__ x,
                 const float* __restrict__ W0, const float* __restrict__ W1,
                 const float* __restrict__ W2, const float* __restrict__ W3)
{
    int blk = blockIdx.x;
    const float* src;
    unsigned short* dst;
    size_t i;
    if (blk < CONV_A_BLOCKS) {
        src = x;
        dst = (unsigned short*)gA;
        i = ((size_t)blk * 256 + threadIdx.x) * 4;
    } else {
        int wblk = blk - CONV_A_BLOCKS;
        int wsel = wblk >> 10;                 // 1024 blocks per matrix
        src = (wsel == 0) ? W0 : (wsel == 1) ? W1 : (wsel == 2) ? W2 : W3;
        dst = (unsigned short*)(gW + (size_t)wsel * 1024 * 1024);
        i = ((size_t)(wblk & 1023) * 256 + threadIdx.x) * 4;
    }
    float4 v = *(const float4*)(src + i);
    ushort4 h;
    h.x = __half_as_ushort(__float2half_rn(v.x));
    h.y = __half_as_ushort(__float2half_rn(v.y));
    h.z = __half_as_ushort(__float2half_rn(v.z));
    h.w = __half_as_ushort(__float2half_rn(v.w));
    *(ushort4*)(dst + i) = h;
}

// ---------------------------------------------------------------------------
// fp16 HMMA GEMM: C = A[M,K] @ W[K,N]. CTA 128x128, BK=32, 4-stage cp.async,
// 4 warps (64x64 warp tiles), 3 CTAs/SM.
// ---------------------------------------------------------------------------
#define ASTRIDE 40
#define BSTRIDE 136
#define A_SM    (128 * ASTRIDE * 2)      // 10240
#define B_SM    (32 * BSTRIDE * 2)       // 8704
#define STAGE_BYTES (A_SM + B_SM)        // 18944
#define GEMM_SMEM (4 * STAGE_BYTES)      // 75776

__device__ __forceinline__ void gemm_load_stage(
    uint32_t sb, int t, int m0, int n0, int kt,
    const __half* pA, const __half* pB)
{
    int k0 = kt * 32;
#pragma unroll
    for (int it = 0; it < 4; it++) {
        int idx = t + it * 128;
        int row = idx >> 2, c8 = (idx & 3) << 3;
        cp_async16(sb + (uint32_t)(row * ASTRIDE + c8) * 2,
                   pA + (size_t)(m0 + row) * 1024 + k0 + c8);
    }
#pragma unroll
    for (int it = 0; it < 4; it++) {
        int idx = t + it * 128;
        int row = idx >> 4, c8 = (idx & 15) << 3;
        cp_async16(sb + A_SM + (uint32_t)(row * BSTRIDE + c8) * 2,
                   pB + (size_t)(k0 + row) * 1024 + n0 + c8);
    }
    asm volatile("cp.async.commit_group;" ::: "memory");
}

__global__ __launch_bounds__(128, 3)
void mma_gemm_kernel(int wsel, float* __restrict__ Cext, int csel, int fmap)
{
    extern __shared__ __half smh[];
    if (wsel < 0) { wsel = blockIdx.z; csel = blockIdx.z; fmap = (blockIdx.z < 2); }

    const __half* pA = gA;
    const __half* pB = gW + (size_t)wsel * 1024 * 1024;

    int t = threadIdx.x, lane = t & 31, wid = t >> 5;
    int n0 = blockIdx.x * 128;
    int m0 = blockIdx.y * 128;
    uint32_t sbase = smem_u32(smh);

    int wm = (wid >> 1) * 64;
    int wn = (wid & 1) * 64;

    float acc[4][8][4];
#pragma unroll
    for (int mi = 0; mi < 4; mi++)
#pragma unroll
        for (int nt = 0; nt < 8; nt++)
#pragma unroll
            for (int q = 0; q < 4; q++) acc[mi][nt][q] = 0.f;

    gemm_load_stage(sbase, t, m0, n0, 0, pA, pB);
    gemm_load_stage(sbase + STAGE_BYTES, t, m0, n0, 1, pA, pB);
    gemm_load_stage(sbase + 2 * STAGE_BYTES, t, m0, n0, 2, pA, pB);

    for (int kt = 0; kt < 32; kt++) {
        if (kt <= 29)      asm volatile("cp.async.wait_group 2;" ::: "memory");
        else if (kt == 30) asm volatile("cp.async.wait_group 1;" ::: "memory");
        else               asm volatile("cp.async.wait_group 0;" ::: "memory");
        __syncthreads();
        if (kt + 3 < 32)
            gemm_load_stage(sbase + (uint32_t)((kt + 3) & 3) * STAGE_BYTES,
                            t, m0, n0, kt + 3, pA, pB);

        uint32_t sb = sbase + (uint32_t)(kt & 3) * STAGE_BYTES;
#pragma unroll
        for (int ks = 0; ks < 2; ks++) {
            uint32_t aF[4][4], bF[16];
            int arow = lane & 15;
            int acol = ks * 16 + ((lane >> 4) << 3);
#pragma unroll
            for (int mi = 0; mi < 4; mi++)
                ldsm_x4(aF[mi], sb + (uint32_t)((wm + mi * 16 + arow) * ASTRIDE + acol) * 2);

            int brow = ks * 16 + (lane & 15);
#pragma unroll
            for (int p = 0; p < 4; p++) {
                int bcol = wn + p * 16 + ((lane >> 4) << 3);
                ldsm_x4_t(&bF[p * 4], sb + A_SM + (uint32_t)(brow * BSTRIDE + bcol) * 2);
            }
#pragma unroll
            for (int mi = 0; mi < 4; mi++)
#pragma unroll
                for (int nt = 0; nt < 8; nt++)
                    mma16816(acc[mi][nt], aF[mi],
                             bF[(nt >> 1) * 4 + (nt & 1) * 2], bF[(nt >> 1) * 4 + (nt & 1) * 2 + 1]);
        }
    }

    int rbase = m0 + wm + (lane >> 2);
    int cb0 = wn + (lane & 3) * 2;
#pragma unroll
    for (int mi = 0; mi < 4; mi++) {
        int row = rbase + mi * 16;
#pragma unroll
        for (int nt = 0; nt < 8; nt++) {
            float v0 = acc[mi][nt][0], v1 = acc[mi][nt][1];
            float v2 = acc[mi][nt][2], v3 = acc[mi][nt][3];
            if (fmap) {
                v0 = v0 > 0.f ? v0 + 1.f : expf(v0);
                v1 = v1 > 0.f ? v1 + 1.f : expf(v1);
                v2 = v2 > 0.f ? v2 + 1.f : expf(v2);
                v3 = v3 > 0.f ? v3 + 1.f : expf(v3);
            }
            if (csel < 3) {
                __half* Ch = (csel == 0) ? g_Qh : (csel == 1) ? g_Kh : g_Vh;
                *(uint32_t*)((unsigned short*)Ch + (size_t)row * 1024 + n0 + cb0 + nt * 8)
                    = pack_h2(v0, v1);
                *(uint32_t*)((unsigned short*)Ch + (size_t)(row + 8) * 1024 + n0 + cb0 + nt * 8)
                    = pack_h2(v2, v3);
            } else {
                float2 o0; o0.x = v0; o0.y = v1;
                float2 o1; o1.x = v2; o1.y = v3;
                *(float2*)(Cext + (size_t)row * 1024 + n0 + cb0 + nt * 8) = o0;
                *(float2*)(Cext + (size_t)(row + 8) * 1024 + n0 + cb0 + nt * 8) = o1;
            }
        }
    }
}

// ---------------------------------------------------------------------------
// Phase A (tensor): S_c = K_c^T V_c (64x64 fp32), z_c = col sums of K.
// ---------------------------------------------------------------------------
#define PA_STRIDE 72

__global__ __launch_bounds__(128)
void phaseA_kernel()
{
    __shared__ __half Ks[128 * PA_STRIDE];
    __shared__ __half Vs[128 * PA_STRIDE];

    int blk = blockIdx.x;
    int c   = blk & (NCv - 1);
    int bh  = blk >> 5;
    int h   = bh & (Hv - 1);
    int b   = bh >> 4;
    int t   = threadIdx.x;
    int lane = t & 31, wid = t >> 5;

    size_t base = ((size_t)(b * Tv + c * Cv)) * Dv + h * HDv;

    for (int idx = t; idx < 128 * 8; idx += 128) {
        int row = idx >> 3, c8 = (idx & 7) << 3;
        size_t go = base + (size_t)row * Dv + c8;
        *(uint4*)&Ks[row * PA_STRIDE + c8] = *(const uint4*)((const unsigned short*)g_Kh + go);
        *(uint4*)&Vs[row * PA_STRIDE + c8] = *(const uint4*)((const unsigned short*)g_Vh + go);
    }
    __syncthreads();

    if (t < 64) {
        float s = 0.f;
        for (int tt = 0; tt < 128; tt++) s += __half2float(Ks[tt * PA_STRIDE + t]);
        g_z[(size_t)(bh * NCv + c) * HDv + t] = s;
    }

    uint32_t ksb = smem_u32(Ks);
    uint32_t vsb = smem_u32(Vs);

    int wm = wid * 16;
    float cS[8][4];
#pragma unroll
    for (int nb = 0; nb < 8; nb++)
#pragma unroll
        for (int q = 0; q < 4; q++) cS[nb][q] = 0.f;

    int a_rofs = ((lane >> 4) << 3) + (lane & 7);
    int a_cofs = wm + (((lane >> 3) & 1) << 3);
    int brow = lane & 15, bcol8 = (lane >> 4) << 3;

#pragma unroll
    for (int ks = 0; ks < 8; ks++) {
        uint32_t a[4];
        ldsm_x4_t(a, ksb + (uint32_t)((ks * 16 + a_rofs) * PA_STRIDE + a_cofs) * 2);
#pragma unroll
        for (int p = 0; p < 4; p++) {
            uint32_t r[4];
            ldsm_x4_t(r, vsb + (uint32_t)((ks * 16 + brow) * PA_STRIDE + p * 16 + bcol8) * 2);
            mma16816(cS[2 * p],     a, r[0], r[1]);
            mma16816(cS[2 * p + 1], a, r[2], r[3]);
        }
    }

    float* Sg = g_S + ((size_t)(bh * NCv + c)) * (HDv * HDv);
    int d0 = wm + (lane >> 2);
    int e0 = (lane & 3) * 2;
#pragma unroll
    for (int nb = 0; nb < 8; nb++) {
        Sg[d0 * 64 + nb * 8 + e0]           = cS[nb][0];
        Sg[d0 * 64 + nb * 8 + e0 + 1]       = cS[nb][1];
        Sg[(d0 + 8) * 64 + nb * 8 + e0]     = cS[nb][2];
        Sg[(d0 + 8) * 64 + nb * 8 + e0 + 1] = cS[nb][3];
    }
}

// ---------------------------------------------------------------------------
// Phase B v2: register-resident exclusive prefix scan over the 32 chunks.
// grid (64 bh, 16 groups), 256 threads; one element-scan per thread.
// All 32 strided loads issued before the serial add chain (MLP=32).
// ---------------------------------------------------------------------------
__global__ __launch_bounds__(256)
void phaseB_kernel()
{
    int bh  = blockIdx.x;
    int grp = blockIdx.y;
    int t   = threadIdx.x;
    int idx = grp * 256 + t;                      // element in 64x64 state

    float* Sg = g_S + (size_t)bh * NCv * (HDv * HDv) + idx;
    float v[NCv];
#pragma unroll
    for (int c = 0; c < NCv; c++) v[c] = Sg[c * (HDv * HDv)];
    float run = 0.f;
#pragma unroll
    for (int c = 0; c < NCv; c++) {
        float x = v[c];
        Sg[c * (HDv * HDv)] = run;
        run += x;
    }

    if (grp == 0 && t < HDv) {
        float* zg = g_z + (size_t)bh * NCv * HDv + t;
        float zv[NCv];
#pragma unroll
        for (int c = 0; c < NCv; c++) zv[c] = zg[c * HDv];
        float rz = 0.f;
#pragma unroll
        for (int c = 0; c < NCv; c++) {
            float x = zv[c];
            zg[c * HDv] = rz;
            rz += x;
        }
    }
}

// ---------------------------------------------------------------------------
// Phase C (tensor): P = tril(QK^T); den = rowsum(P)+Q·z+eps;
// O = (P·V + Q·S_prev)/den, written fp16 into gA.
// ---------------------------------------------------------------------------
#define QS_STRIDE 72
#define PHC_SMEM ((3 * 128 * QS_STRIDE + 64 * QS_STRIDE) * 2 + 64 * 4)

__global__ __launch_bounds__(256)
void phaseC_kernel()
{
    extern __shared__ __half smc[];
    __half* Qs = smc;
    __half* Ks = smc + 128 * QS_STRIDE;
    __half* Vs = smc + 2 * 128 * QS_STRIDE;
    __half* Sh = smc + 3 * 128 * QS_STRIDE;
    float*  zf = (float*)(smc + 3 * 128 * QS_STRIDE + 64 * QS_STRIDE);

    int blk = blockIdx.x;
    int c   = blk & (NCv - 1);
    int bh  = blk >> 5;
    int h   = bh & (Hv - 1);
    int b   = bh >> 4;
    int t   = threadIdx.x;
    int lane = t & 31, wid = t >> 5;

    size_t base = ((size_t)(b * Tv + c * Cv)) * Dv + h * HDv;

    for (int idx = t; idx < 128 * 8; idx += 256) {
        int row = idx >> 3, c8 = (idx & 7) << 3;
        size_t go = base + (size_t)row * Dv + c8;
        uint32_t so = (uint32_t)(row * QS_STRIDE + c8);
        *(uint4*)&Qs[so] = *(const uint4*)((const unsigned short*)g_Qh + go);
        *(uint4*)&Ks[so] = *(const uint4*)((const unsigned short*)g_Kh + go);
        *(uint4*)&Vs[so] = *(const uint4*)((const unsigned short*)g_Vh + go);
    }
    const float* Sg = g_S + ((size_t)(bh * NCv + c)) * (HDv * HDv);
    for (int idx = t; idx < 4096; idx += 256) {
        int d = idx >> 6, e = idx & 63;
        Sh[d * QS_STRIDE + e] = __float2half_rn(Sg[idx]);
    }
    if (t < 64) zf[t] = g_z[(size_t)(bh * NCv + c) * HDv + t];
    __syncthreads();

    uint32_t qsb = smem_u32(Qs), ksb = smem_u32(Ks), vsb = smem_u32(Vs), shb = smem_u32(Sh);

    int i0 = wid * 16;
    int arow = lane & 15, acol8 = (lane >> 4) << 3;

    uint32_t aQ[4][4];
#pragma unroll
    for (int ks = 0; ks < 4; ks++)
        ldsm_x4(aQ[ks], qsb + (uint32_t)((i0 + arow) * QS_STRIDE + ks * 16 + acol8) * 2);

    float cP[16][4];
#pragma unroll
    for (int nb = 0; nb < 16; nb++)
#pragma unroll
        for (int q = 0; q < 4; q++) cP[nb][q] = 0.f;

#pragma unroll
    for (int ks = 0; ks < 4; ks++) {
#pragma unroll
        for (int jb = 0; jb < 8; jb++) {
            uint32_t r[4];
            ldsm_x4(r, ksb + (uint32_t)((jb * 16 + arow) * QS_STRIDE + ks * 16 + acol8) * 2);
            mma16816(cP[2 * jb],     aQ[ks], r[0], r[2]);
            mma16816(cP[2 * jb + 1], aQ[ks], r[1], r[3]);
        }
    }

    int r0 = i0 + (lane >> 2);
    int cb = (lane & 3) * 2;
    float rs0 = 0.f, rs1 = 0.f;
#pragma unroll
    for (int nb = 0; nb < 16; nb++) {
        int j0 = nb * 8 + cb;
        if (j0     > r0)     cP[nb][0] = 0.f;
        if (j0 + 1 > r0)     cP[nb][1] = 0.f;
        if (j0     > r0 + 8) cP[nb][2] = 0.f;
        if (j0 + 1 > r0 + 8) cP[nb][3] = 0.f;
        rs0 += cP[nb][0] + cP[nb][1];
        rs1 += cP[nb][2] + cP[nb][3];
    }
    rs0 += __shfl_xor_sync(0xffffffffu, rs0, 1);
    rs0 += __shfl_xor_sync(0xffffffffu, rs0, 2);
    rs1 += __shfl_xor_sync(0xffffffffu, rs1, 1);
    rs1 += __shfl_xor_sync(0xffffffffu, rs1, 2);

    float qz0 = 0.f, qz1 = 0.f;
    for (int d = 0; d < 64; d++) {
        float zz = zf[d];
        qz0 += __half2float(Qs[r0 * QS_STRIDE + d]) * zz;
        qz1 += __half2float(Qs[(r0 + 8) * QS_STRIDE + d]) * zz;
    }
    float inv0 = 1.f / (rs0 + qz0 + 1e-6f);
    float inv1 = 1.f / (rs1 + qz1 + 1e-6f);

    uint32_t aP[8][4];
#pragma unroll
    for (int jk = 0; jk < 8; jk++) {
        aP[jk][0] = pack_h2(cP[2 * jk][0],     cP[2 * jk][1]);
        aP[jk][1] = pack_h2(cP[2 * jk][2],     cP[2 * jk][3]);
        aP[jk][2] = pack_h2(cP[2 * jk + 1][0], cP[2 * jk + 1][1]);
        aP[jk][3] = pack_h2(cP[2 * jk + 1][2], cP[2 * jk + 1][3]);
    }

    float cO[8][4];
#pragma unroll
    for (int nb = 0; nb < 8; nb++)
#pragma unroll
        for (int q = 0; q < 4; q++) cO[nb][q] = 0.f;

#pragma unroll
    for (int jk = 0; jk < 8; jk++) {
#pragma unroll
        for (int p = 0; p < 4; p++) {
            uint32_t r[4];
            ldsm_x4_t(r, vsb + (uint32_t)((jk * 16 + arow) * QS_STRIDE + p * 16 + acol8) * 2);
            mma16816(cO[2 * p],     aP[jk], r[0], r[1]);
            mma16816(cO[2 * p + 1], aP[jk], r[2], r[3]);
        }
    }
#pragma unroll
    for (int ks = 0; ks < 4; ks++) {
#pragma unroll
        for (int p = 0; p < 4; p++) {
            uint32_t r[4];
            ldsm_x4_t(r, shb + (uint32_t)((ks * 16 + arow) * QS_STRIDE + p * 16 + acol8) * 2);
            mma16816(cO[2 * p],     aQ[ks], r[0], r[1]);
            mma16816(cO[2 * p + 1], aQ[ks], r[2], r[3]);
        }
    }

    unsigned short* Yg = (unsigned short*)gA + base;
#pragma unroll
    for (int nb = 0; nb < 8; nb++) {
        int e = nb * 8 + cb;
        *(uint32_t*)(Yg + (size_t)r0 * Dv + e)       = pack_h2(cO[nb][0] * inv0, cO[nb][1] * inv0);
        *(uint32_t*)(Yg + (size_t)(r0 + 8) * Dv + e) = pack_h2(cO[nb][2] * inv1, cO[nb][3] * inv1);
    }
}

// ---------------------------------------------------------------------------
// Launch
// ---------------------------------------------------------------------------
extern "C" void kernel_launch(void* const* d_in, const int* in_sizes, int n_in,
                              void* d_out, int out_size)
{
    const float* x  = (const float*)d_in[0];
    const float* Wq = (const float*)d_in[1];
    const float* Wk = (const float*)d_in[2];
    const float* Wv = (const float*)d_in[3];
    const float* Wo = (const float*)d_in[4];
    float* out = (float*)d_out;

    cudaFuncSetAttribute(mma_gemm_kernel,
                         cudaFuncAttributeMaxDynamicSharedMemorySize, GEMM_SMEM);
    cudaFuncSetAttribute(phaseC_kernel,
                         cudaFuncAttributeMaxDynamicSharedMemorySize, PHC_SMEM);

    conv_kernel<<<CONV_A_BLOCKS + CONV_W_BLOCKS, 256>>>(x, Wq, Wk, Wv, Wo);

    dim3 gqkv(1024 / 128, Mv / 128, 3);
    mma_gemm_kernel<<<gqkv, 128, GEMM_SMEM>>>(-1, nullptr, 0, 0);  // fp16 Q/K/V

    phaseA_kernel<<<Bv * Hv * NCv, 128>>>();
    dim3 gb(Bv * Hv, 16);
    phaseB_kernel<<<gb, 256>>>();
    phaseC_kernel<<<Bv * Hv * NCv, 256, PHC_SMEM>>>();             // fp16 Y into gA

    dim3 go(1024 / 128, Mv / 128);
    mma_gemm_kernel<<<go, 128, GEMM_SMEM>>>(3, out, 3, 0);         // out = Y@Wo
}